// round 6
// baseline (speedup 1.0000x reference)
#include <cuda_runtime.h>
#include <math.h>
#include <stdint.h>

#define B_   512
#define T_   128
#define N_   500
#define H_   1024
#define G3_  3072
#define BT_  65536

typedef unsigned long long ull;

// ===================== static device scratch =====================
__device__ float g_xproj[(size_t)BT_ * G3_];
__device__ float g_seq  [(size_t)BT_ * H_];
__device__ float g_h0   [(size_t)B_ * H_];
__device__ float g_h1   [(size_t)B_ * H_];
__device__ float g_z    [(size_t)B_ * H_];
__device__ float g_za   [(size_t)B_ * H_];
__device__ float g_scores[(size_t)B_ * N_];
__device__ float g_wih0p[(size_t)G3_ * N_];
__device__ float g_whh0p[(size_t)G3_ * H_];
__device__ float g_wih1p[(size_t)G3_ * H_];
__device__ float g_whh1p[(size_t)G3_ * H_];
__device__ float g_bih0p[G3_];
__device__ float g_bhh0p[G3_];
__device__ float g_bih1p[G3_];
__device__ float g_bhh1p[G3_];

// ===================== helpers =====================
__device__ __forceinline__ float t32(float a) {
    uint32_t u;
    asm("cvt.rna.tf32.f32 %0, %1;" : "=r"(u) : "f"(a));
    return __uint_as_float(u);
}
__device__ __forceinline__ float sigf(float x) { return 1.f / (1.f + __expf(-x)); }

__device__ __forceinline__ void mma8(float* c, const uint32_t* a, const uint32_t* b) {
    asm volatile(
        "mma.sync.aligned.m16n8k8.row.col.f32.tf32.tf32.f32 "
        "{%0,%1,%2,%3}, {%4,%5,%6,%7}, {%8,%9}, {%0,%1,%2,%3};"
        : "+f"(c[0]), "+f"(c[1]), "+f"(c[2]), "+f"(c[3])
        : "r"(a[0]), "r"(a[1]), "r"(a[2]), "r"(a[3]), "r"(b[0]), "r"(b[1]));
}

// ===================== exact-3-way-split TF32 GEMM, per-tile RN accumulation ====
// a = h + l + m exactly; all 6 kept products are exact in fp32. Each K-tile gets
// a FRESH mma accumulator (limits in-tensor-core truncated accumulation to 24
// adds); tiles are folded into a master accumulator with RN FADDs.
#define TM 128
#define TN 96
#define KT 32

// smem float offsets, row stride 36 (32 + 4 pad)
#define A2H 0            // [128][36]
#define A2L 4608
#define A2M 9216
#define B2H 13824        // [96][36]
#define B2L 17280
#define B2M 20736
#define EPI_ 0           // overlay after mainloop: [128][100]
#define SMEMF 24192
#define SMEMSZ (SMEMF * 4)

__device__ __forceinline__ void loadA(const float* __restrict__ A, int Kdim,
                                      int m0, int k0, float4* Apre)
{
    #pragma unroll
    for (int j = 0; j < 4; j++) {
        int i = threadIdx.x + j * 256;
        int row = i >> 3;
        int gk = k0 + (i & 7) * 4;
        Apre[j] = (gk < Kdim) ? __ldg((const float4*)(A + (size_t)(m0 + row) * Kdim + gk))
                              : make_float4(0.f, 0.f, 0.f, 0.f);
    }
}
__device__ __forceinline__ void loadB(const float* __restrict__ W, int Kdim,
                                      int n0, int k0, float4* Bpre)
{
    #pragma unroll
    for (int j = 0; j < 3; j++) {
        int i = threadIdx.x + j * 256;
        int row = i >> 3;
        int gk = k0 + (i & 7) * 4;
        Bpre[j] = (gk < Kdim) ? __ldg((const float4*)(W + (size_t)(n0 + row) * Kdim + gk))
                              : make_float4(0.f, 0.f, 0.f, 0.f);
    }
}

__device__ __forceinline__ void split_sts(float* sm, int baseH, int baseL, int baseM,
                                          int o, float4 v)
{
    float4 h, l, mm;
    h.x = t32(v.x); h.y = t32(v.y); h.z = t32(v.z); h.w = t32(v.w);
    float rx = v.x - h.x, ry = v.y - h.y, rz = v.z - h.z, rw = v.w - h.w;
    l.x = t32(rx); l.y = t32(ry); l.z = t32(rz); l.w = t32(rw);
    mm.x = rx - l.x; mm.y = ry - l.y; mm.z = rz - l.z; mm.w = rw - l.w;
    *(float4*)&sm[baseH + o] = h;
    *(float4*)&sm[baseL + o] = l;
    *(float4*)&sm[baseM + o] = mm;
}

// mode 0: write C (row stride G3_) + bias
// mode 1: fused GRU step (gh + gates -> hout/seq)
__global__ __launch_bounds__(256, 1)
void mma_gemm(const float* __restrict__ A, const float* __restrict__ W,
              const float* __restrict__ bias,
              float* __restrict__ C,
              const float* __restrict__ xp, const float* __restrict__ hin,
              float* __restrict__ hout, float* __restrict__ seqp,
              int Kdim, int t, int mode)
{
    extern __shared__ __align__(16) float sm[];
    uint32_t* smu = (uint32_t*)sm;

    const int tid = threadIdx.x;
    const int wid = tid >> 5, lane = tid & 31;
    const int gid = lane >> 2, tig = lane & 3;
    const int wm = (wid >> 2) * 64;          // warp m offset (0 or 64)
    const int wn = (wid & 3) * 24;           // warp n offset (0,24,48,72)
    const int m0 = blockIdx.y * TM, n0 = blockIdx.x * TN;

    float master[4][3][4];
    #pragma unroll
    for (int i = 0; i < 4; i++)
        #pragma unroll
        for (int j = 0; j < 3; j++)
            #pragma unroll
            for (int q = 0; q < 4; q++) master[i][j][q] = 0.f;

    float4 Apre[4], Bpre[3];
    const int ntiles = (Kdim + KT - 1) / KT;
    loadA(A, Kdim, m0, 0, Apre);
    loadB(W, Kdim, n0, 0, Bpre);

    for (int kt = 0; kt < ntiles; kt++) {
        // --- STS with exact 3-way tf32 split ---
        #pragma unroll
        for (int j = 0; j < 4; j++) {
            int i = tid + j * 256;
            int o = (i >> 3) * 36 + (i & 7) * 4;
            split_sts(sm, A2H, A2L, A2M, o, Apre[j]);
        }
        #pragma unroll
        for (int j = 0; j < 3; j++) {
            int i = tid + j * 256;
            int o = (i >> 3) * 36 + (i & 7) * 4;
            split_sts(sm, B2H, B2L, B2M, o, Bpre[j]);
        }
        __syncthreads();

        if (kt + 1 < ntiles) {
            loadA(A, Kdim, m0, (kt + 1) * KT, Apre);
            loadB(W, Kdim, n0, (kt + 1) * KT, Bpre);
        }

        // --- fresh per-tile accumulator ---
        float acc[4][3][4];
        #pragma unroll
        for (int i = 0; i < 4; i++)
            #pragma unroll
            for (int j = 0; j < 3; j++)
                #pragma unroll
                for (int q = 0; q < 4; q++) acc[i][j][q] = 0.f;

        #pragma unroll
        for (int ks = 0; ks < KT; ks += 8) {
            uint32_t bh[3][2], bl[3][2], bm[3][2];
            #pragma unroll
            for (int f = 0; f < 3; f++) {
                int r0 = (wn + 8 * f + gid) * 36 + ks + tig;
                bh[f][0] = smu[B2H + r0]; bh[f][1] = smu[B2H + r0 + 4];
                bl[f][0] = smu[B2L + r0]; bl[f][1] = smu[B2L + r0 + 4];
                bm[f][0] = smu[B2M + r0]; bm[f][1] = smu[B2M + r0 + 4];
            }
            #pragma unroll
            for (int fm = 0; fm < 4; fm++) {
                uint32_t ah[4], al[4], am_[4];
                int r0 = (wm + 16 * fm + gid) * 36 + ks + tig;
                ah[0] = smu[A2H + r0]; ah[1] = smu[A2H + r0 + 288];
                ah[2] = smu[A2H + r0 + 4]; ah[3] = smu[A2H + r0 + 292];
                al[0] = smu[A2L + r0]; al[1] = smu[A2L + r0 + 288];
                al[2] = smu[A2L + r0 + 4]; al[3] = smu[A2L + r0 + 292];
                am_[0] = smu[A2M + r0]; am_[1] = smu[A2M + r0 + 288];
                am_[2] = smu[A2M + r0 + 4]; am_[3] = smu[A2M + r0 + 292];
                #pragma unroll
                for (int fn = 0; fn < 3; fn++) {
                    mma8(acc[fm][fn], ah, bh[fn]);
                    mma8(acc[fm][fn], ah, bl[fn]);
                    mma8(acc[fm][fn], al, bh[fn]);
                    mma8(acc[fm][fn], al, bl[fn]);
                    mma8(acc[fm][fn], ah, bm[fn]);
                    mma8(acc[fm][fn], am_, bh[fn]);
                }
            }
        }

        // --- fold tile into master with RN adds ---
        #pragma unroll
        for (int i = 0; i < 4; i++)
            #pragma unroll
            for (int j = 0; j < 3; j++)
                #pragma unroll
                for (int q = 0; q < 4; q++) master[i][j][q] += acc[i][j][q];

        __syncthreads();
    }

    // --- write fragments to SMEM epilogue tile [128][100] ---
    #pragma unroll
    for (int fm = 0; fm < 4; fm++) {
        int row = wm + 16 * fm + gid;
        #pragma unroll
        for (int fn = 0; fn < 3; fn++) {
            int col = wn + 8 * fn + 2 * tig;
            *(float2*)&sm[EPI_ + row * 100 + col] =
                make_float2(master[fm][fn][0], master[fm][fn][1]);
            *(float2*)&sm[EPI_ + (row + 8) * 100 + col] =
                make_float2(master[fm][fn][2], master[fm][fn][3]);
        }
    }
    __syncthreads();

    if (mode == 0) {
        int row = tid >> 1, half = tid & 1;
        int cb = half * 48;
        float* cp = C + (size_t)(m0 + row) * G3_ + n0 + cb;
        #pragma unroll
        for (int j = 0; j < 12; j++) {
            float4 v = *(float4*)&sm[EPI_ + row * 100 + cb + j * 4];
            float4 bb = *(const float4*)&bias[n0 + cb + j * 4];
            v.x += bb.x; v.y += bb.y; v.z += bb.z; v.w += bb.w;
            *(float4*)(cp + j * 4) = v;
        }
    } else {
        #pragma unroll
        for (int it = 0; it < 16; it++) {
            int unit = tid + it * 256;
            int u = unit & 31;          // triple index 0..31
            int row = unit >> 5;        // 0..127
            int b = m0 + row;
            int c0 = 3 * u;
            float gr = sm[EPI_ + row * 100 + c0]     + bias[n0 + c0];
            float gz = sm[EPI_ + row * 100 + c0 + 1] + bias[n0 + c0 + 1];
            float gn = sm[EPI_ + row * 100 + c0 + 2] + bias[n0 + c0 + 2];
            const float* xr = xp + ((size_t)b * T_ + t) * G3_ + n0 + c0;
            float r  = sigf(xr[0] + gr);
            float z  = sigf(xr[1] + gz);
            float nn = tanhf(xr[2] + r * gn);
            int hu = n0 / 3 + u;
            float hp = hin[(size_t)b * H_ + hu];
            float hv = (1.f - z) * nn + z * hp;
            hout[(size_t)b * H_ + hu] = hv;
            if (seqp) seqp[((size_t)b * T_ + t) * H_ + hu] = hv;
        }
    }
}

// ===================== FFMA2 GEMM (head only) =====================
#define BM 128
#define BN 96
#define BK 16
#define NT 256

__device__ __forceinline__ ull pack2(float lo, float hi) {
    ull r; asm("mov.b64 %0, {%1, %2};" : "=l"(r) : "f"(lo), "f"(hi)); return r;
}
__device__ __forceinline__ float2 unpack2(ull v) {
    float2 r; asm("mov.b64 {%0, %1}, %2;" : "=f"(r.x), "=f"(r.y) : "l"(v)); return r;
}
__device__ __forceinline__ void ffma2(ull& d, ull a, ull b) {
    asm("fma.rn.f32x2 %0, %1, %2, %3;" : "=l"(d) : "l"(a), "l"(b), "l"(d));
}

__device__ __forceinline__ void load_tileA(const float* __restrict__ A, int M, int K,
                                           int m0, int k0, int am, int ak, float4* Apre)
{
    #pragma unroll
    for (int r = 0; r < 2; r++) {
        int gm = m0 + am + r * 64;
        int gk = k0 + ak;
        float4 v = make_float4(0.f, 0.f, 0.f, 0.f);
        if (gm < M) {
            if (gk + 3 < K) v = *(const float4*)(A + (size_t)gm * K + gk);
            else {
                if (gk + 0 < K) v.x = A[(size_t)gm * K + gk + 0];
                if (gk + 1 < K) v.y = A[(size_t)gm * K + gk + 1];
                if (gk + 2 < K) v.z = A[(size_t)gm * K + gk + 2];
                if (gk + 3 < K) v.w = A[(size_t)gm * K + gk + 3];
            }
        }
        Apre[r] = v;
    }
}
__device__ __forceinline__ void load_tileB(const float* __restrict__ Bm, int Nd, int K,
                                           int n0, int k0, int tid, float2* Bpre)
{
    #pragma unroll
    for (int j = 0; j < 3; j++) {
        int i2 = tid + j * 256;
        int bn = i2 >> 3;
        int bk = (i2 & 7) << 1;
        int gn = n0 + bn, gk = k0 + bk;
        float2 v = make_float2(0.f, 0.f);
        if (gn < Nd && gk < K) v = *(const float2*)(Bm + (size_t)gn * K + gk);
        Bpre[j] = v;
    }
}

__global__ __launch_bounds__(NT)
void gemm_f2(const float* __restrict__ A, const float* __restrict__ Bm,
             const float* __restrict__ bias, float* __restrict__ C,
             int M, int Nd, int K)
{
    __shared__ float As[BK][BM + 4];
    __shared__ float Bs[BK][BN + 2];
    const int tid = threadIdx.x;
    const int tx = tid & 15, ty = tid >> 4;
    const int m0 = blockIdx.y * BM, n0 = blockIdx.x * BN;
    const int am = tid >> 2;
    const int ak = (tid & 3) << 2;
    ull acc[4][6];
    #pragma unroll
    for (int i = 0; i < 4; i++)
        #pragma unroll
        for (int j = 0; j < 6; j++) acc[i][j] = 0ull;
    float4 Apre[2]; float2 Bpre[3];
    const int ntiles = (K + BK - 1) / BK;
    load_tileA(A, M, K, m0, 0, am, ak, Apre);
    load_tileB(Bm, Nd, K, n0, 0, tid, Bpre);
    for (int kt = 0; kt < ntiles; kt++) {
        #pragma unroll
        for (int r = 0; r < 2; r++) {
            As[ak + 0][am + r * 64] = Apre[r].x;
            As[ak + 1][am + r * 64] = Apre[r].y;
            As[ak + 2][am + r * 64] = Apre[r].z;
            As[ak + 3][am + r * 64] = Apre[r].w;
        }
        #pragma unroll
        for (int j = 0; j < 3; j++) {
            int i2 = tid + j * 256;
            int bn = i2 >> 3, bk = (i2 & 7) << 1;
            Bs[bk][bn]     = Bpre[j].x;
            Bs[bk + 1][bn] = Bpre[j].y;
        }
        __syncthreads();
        if (kt + 1 < ntiles) {
            load_tileA(A, M, K, m0, (kt + 1) * BK, am, ak, Apre);
            load_tileB(Bm, Nd, K, n0, (kt + 1) * BK, tid, Bpre);
        }
        #pragma unroll
        for (int k = 0; k < BK; k++) {
            ull av[4];
            #pragma unroll
            for (int i = 0; i < 4; i++) av[i] = *(const ull*)&As[k][ty * 8 + 2 * i];
            ull bv[6];
            #pragma unroll
            for (int j = 0; j < 6; j++) { float b = Bs[k][tx * 6 + j]; bv[j] = pack2(b, b); }
            #pragma unroll
            for (int i = 0; i < 4; i++)
                #pragma unroll
                for (int j = 0; j < 6; j++) ffma2(acc[i][j], av[i], bv[j]);
        }
        __syncthreads();
    }
    #pragma unroll
    for (int i = 0; i < 4; i++) {
        int gm0 = m0 + ty * 8 + 2 * i;
        #pragma unroll
        for (int j = 0; j < 6; j++) {
            int gn = n0 + tx * 6 + j;
            if (gn >= Nd) continue;
            float2 v = unpack2(acc[i][j]);
            float bb = bias ? bias[gn] : 0.f;
            if (gm0 < M)     C[(size_t)gm0 * Nd + gn]       = v.x + bb;
            if (gm0 + 1 < M) C[(size_t)(gm0 + 1) * Nd + gn] = v.y + bb;
        }
    }
}

// ===================== misc kernels =====================
__global__ void permute_w(const float* __restrict__ w, float* __restrict__ wp, int K)
{
    int c = blockIdx.y;
    int k = blockIdx.x * 256 + threadIdx.x;
    if (k >= K) return;
    int g = c % 3, h = c / 3;
    wp[(size_t)c * K + k] = w[(size_t)(g * H_ + h) * K + k];
}
__global__ void permute_b(const float* __restrict__ b, float* __restrict__ bp)
{
    int c = blockIdx.x * 256 + threadIdx.x;
    if (c < G3_) bp[c] = b[(c % 3) * H_ + c / 3];
}
__global__ void zero_kernel(float* __restrict__ p, int n)
{
    int i = blockIdx.x * blockDim.x + threadIdx.x;
    if (i < n) p[i] = 0.f;
}

__global__ __launch_bounds__(256)
void ln_silu(const float* __restrict__ z,
             const float* __restrict__ lng,
             const float* __restrict__ lnb,
             float* __restrict__ out)
{
    __shared__ float red[256];
    int b = blockIdx.x, tid = threadIdx.x;
    const float* row = z + (size_t)b * H_;
    float s = 0.f, s2 = 0.f;
    for (int i = tid; i < H_; i += 256) { float v = row[i]; s += v; s2 += v * v; }
    red[tid] = s; __syncthreads();
    for (int o = 128; o > 0; o >>= 1) { if (tid < o) red[tid] += red[tid + o]; __syncthreads(); }
    float mu = red[0] / H_;
    __syncthreads();
    red[tid] = s2; __syncthreads();
    for (int o = 128; o > 0; o >>= 1) { if (tid < o) red[tid] += red[tid + o]; __syncthreads(); }
    float var = red[0] / H_ - mu * mu;
    float inv = rsqrtf(var + 1e-5f);
    for (int i = tid; i < H_; i += 256) {
        float y = (row[i] - mu) * inv * lng[i] + lnb[i];
        out[(size_t)b * H_ + i] = y / (1.f + expf(-y));
    }
}

__global__ __launch_bounds__(512)
void softmax_rebalance(const float* __restrict__ scores,
                       float* __restrict__ out)
{
    __shared__ float red[512];
    int b = blockIdx.x, tid = threadIdx.x;
    float s = (tid < N_) ? scores[(size_t)b * N_ + tid] : -INFINITY;
    if (s < 0.f) s = -INFINITY;
    red[tid] = s; __syncthreads();
    for (int o = 256; o > 0; o >>= 1) { if (tid < o) red[tid] = fmaxf(red[tid], red[tid + o]); __syncthreads(); }
    float m = red[0]; __syncthreads();
    float e = (tid < N_) ? expf(s - m) : 0.f;
    red[tid] = e; __syncthreads();
    for (int o = 256; o > 0; o >>= 1) { if (tid < o) red[tid] += red[tid + o]; __syncthreads(); }
    float S = red[0]; __syncthreads();
    float w = e / S;
    w = fminf(fmaxf(w, 0.0f), 0.1f);
    for (int it = 0; it < 20; it++) {
        red[tid] = (tid < N_) ? w : 0.f; __syncthreads();
        for (int o = 256; o > 0; o >>= 1) { if (tid < o) red[tid] += red[tid + o]; __syncthreads(); }
        float tot = red[0]; __syncthreads();
        float excess = tot - 1.0f;
        bool  active = excess > 1e-6f;
        float sur = fmaxf(w - 0.1f, 0.f);
        red[tid] = (tid < N_) ? sur : 0.f; __syncthreads();
        for (int o = 256; o > 0; o >>= 1) { if (tid < o) red[tid] += red[tid + o]; __syncthreads(); }
        float totsur = red[0]; __syncthreads();
        float upd = (totsur > 0.f)
                  ? w - sur / fmaxf(totsur, 1e-12f) * excess
                  : w - excess / (float)N_;
        upd = fminf(fmaxf(upd, 0.0f), 0.1f);
        if (active) w = upd;
    }
    if (tid < N_) out[(size_t)b * N_ + tid] = w;
}

// ===================== orchestration =====================
extern "C" void kernel_launch(void* const* d_in, const int* in_sizes, int n_in,
                              void* d_out, int out_size)
{
    const float* x     = (const float*)d_in[0];
    const float* w_ih0 = (const float*)d_in[1];
    const float* w_hh0 = (const float*)d_in[2];
    const float* b_ih0 = (const float*)d_in[3];
    const float* b_hh0 = (const float*)d_in[4];
    const float* w_ih1 = (const float*)d_in[5];
    const float* w_hh1 = (const float*)d_in[6];
    const float* b_ih1 = (const float*)d_in[7];
    const float* b_hh1 = (const float*)d_in[8];
    const float* w1    = (const float*)d_in[9];
    const float* b1    = (const float*)d_in[10];
    const float* ln_g  = (const float*)d_in[11];
    const float* ln_b  = (const float*)d_in[12];
    const float* w2    = (const float*)d_in[13];
    const float* b2    = (const float*)d_in[14];
    float* out = (float*)d_out;

    void* p;
    float *xproj, *seq, *h0, *h1, *z, *za, *scores;
    float *wih0p, *whh0p, *wih1p, *whh1p, *bih0p, *bhh0p, *bih1p, *bhh1p;
    cudaGetSymbolAddress(&p, g_xproj);  xproj  = (float*)p;
    cudaGetSymbolAddress(&p, g_seq);    seq    = (float*)p;
    cudaGetSymbolAddress(&p, g_h0);     h0     = (float*)p;
    cudaGetSymbolAddress(&p, g_h1);     h1     = (float*)p;
    cudaGetSymbolAddress(&p, g_z);      z      = (float*)p;
    cudaGetSymbolAddress(&p, g_za);     za     = (float*)p;
    cudaGetSymbolAddress(&p, g_scores); scores = (float*)p;
    cudaGetSymbolAddress(&p, g_wih0p);  wih0p  = (float*)p;
    cudaGetSymbolAddress(&p, g_whh0p);  whh0p  = (float*)p;
    cudaGetSymbolAddress(&p, g_wih1p);  wih1p  = (float*)p;
    cudaGetSymbolAddress(&p, g_whh1p);  whh1p  = (float*)p;
    cudaGetSymbolAddress(&p, g_bih0p);  bih0p  = (float*)p;
    cudaGetSymbolAddress(&p, g_bhh0p);  bhh0p  = (float*)p;
    cudaGetSymbolAddress(&p, g_bih1p);  bih1p  = (float*)p;
    cudaGetSymbolAddress(&p, g_bhh1p);  bhh1p  = (float*)p;

    cudaFuncSetAttribute(mma_gemm, cudaFuncAttributeMaxDynamicSharedMemorySize, SMEMSZ);

    // permute weights/biases into gate-interleaved layout (h*3+g)
    permute_w<<<dim3((N_ + 255) / 256, G3_), 256>>>(w_ih0, wih0p, N_);
    permute_w<<<dim3((H_ + 255) / 256, G3_), 256>>>(w_hh0, whh0p, H_);
    permute_w<<<dim3((H_ + 255) / 256, G3_), 256>>>(w_ih1, wih1p, H_);
    permute_w<<<dim3((H_ + 255) / 256, G3_), 256>>>(w_hh1, whh1p, H_);
    permute_b<<<(G3_ + 255) / 256, 256>>>(b_ih0, bih0p);
    permute_b<<<(G3_ + 255) / 256, 256>>>(b_hh0, bhh0p);
    permute_b<<<(G3_ + 255) / 256, 256>>>(b_ih1, bih1p);
    permute_b<<<(G3_ + 255) / 256, 256>>>(b_hh1, bhh1p);

    // layer 0 input projection
    mma_gemm<<<dim3(G3_ / TN, BT_ / TM), 256, SMEMSZ>>>(
        x, wih0p, bih0p, xproj, nullptr, nullptr, nullptr, nullptr, N_, 0, 0);
    zero_kernel<<<(B_ * H_ + 255) / 256, 256>>>(h0, B_ * H_);

    // layer 0 recurrence (fused GEMM + gates)
    for (int t = 0; t < T_; t++) {
        float* hin  = (t & 1) ? h1 : h0;
        float* hout = (t & 1) ? h0 : h1;
        mma_gemm<<<dim3(G3_ / TN, B_ / TM), 256, SMEMSZ>>>(
            hin, whh0p, bhh0p, nullptr, xproj, hin, hout, seq, H_, t, 1);
    }

    // layer 1 input projection
    mma_gemm<<<dim3(G3_ / TN, BT_ / TM), 256, SMEMSZ>>>(
        seq, wih1p, bih1p, xproj, nullptr, nullptr, nullptr, nullptr, H_, 0, 0);
    zero_kernel<<<(B_ * H_ + 255) / 256, 256>>>(h0, B_ * H_);

    // layer 1 recurrence
    for (int t = 0; t < T_; t++) {
        float* hin  = (t & 1) ? h1 : h0;
        float* hout = (t & 1) ? h0 : h1;
        mma_gemm<<<dim3(G3_ / TN, B_ / TM), 256, SMEMSZ>>>(
            hin, whh1p, bhh1p, nullptr, xproj, hin, hout, nullptr, H_, t, 1);
    }

    // head (FFMA2 path; tiny)
    gemm_f2<<<dim3((H_ + BN - 1) / BN, B_ / BM), NT>>>(h0, w1, b1, z, B_, H_, H_);
    ln_silu<<<B_, 256>>>(z, ln_g, ln_b, za);
    gemm_f2<<<dim3((N_ + BN - 1) / BN, B_ / BM), NT>>>(za, w2, b2, scores, B_, N_, H_);
    softmax_rebalance<<<B_, 512>>>(scores, out);
}

// round 7
// speedup vs baseline: 1.0004x; 1.0004x over previous
#include <cuda_runtime.h>
#include <math.h>
#include <stdint.h>

#define B_   512
#define T_   128
#define N_   500
#define H_   1024
#define G3_  3072
#define BT_  65536

typedef unsigned long long ull;

// ===================== static device scratch =====================
__device__ float g_xproj[(size_t)BT_ * G3_];
__device__ float g_seq  [(size_t)BT_ * H_];
__device__ float g_h0   [(size_t)B_ * H_];
__device__ float g_h1   [(size_t)B_ * H_];
__device__ float g_z    [(size_t)B_ * H_];
__device__ float g_za   [(size_t)B_ * H_];
__device__ float g_scores[(size_t)B_ * N_];
__device__ float g_wih0p[(size_t)G3_ * N_];
__device__ float g_whh0p[(size_t)G3_ * H_];
__device__ float g_wih1p[(size_t)G3_ * H_];
__device__ float g_whh1p[(size_t)G3_ * H_];
__device__ float g_bih0p[G3_];
__device__ float g_bhh0p[G3_];
__device__ float g_bih1p[G3_];
__device__ float g_bhh1p[G3_];

// ===================== helpers =====================
__device__ __forceinline__ float t32(float a) {
    uint32_t u;
    asm("cvt.rna.tf32.f32 %0, %1;" : "=r"(u) : "f"(a));
    return __uint_as_float(u);
}
__device__ __forceinline__ float sigf(float x) { return 1.f / (1.f + __expf(-x)); }

__device__ __forceinline__ void mma8(float* c, const uint32_t* a, const uint32_t* b) {
    asm volatile(
        "mma.sync.aligned.m16n8k8.row.col.f32.tf32.tf32.f32 "
        "{%0,%1,%2,%3}, {%4,%5,%6,%7}, {%8,%9}, {%0,%1,%2,%3};"
        : "+f"(c[0]), "+f"(c[1]), "+f"(c[2]), "+f"(c[3])
        : "r"(a[0]), "r"(a[1]), "r"(a[2]), "r"(a[3]), "r"(b[0]), "r"(b[1]));
}

// ===================== exact-3-way-split TF32 GEMM, per-tile RN accumulation ====
// a = h + l + m exactly; all 6 kept products are exact in fp32. Each K-tile gets
// a FRESH mma accumulator (limits in-tensor-core truncated accumulation to 24
// adds); tiles are folded into a master accumulator with RN FADDs.
#define TM 128
#define TN 96
#define KT 32

// smem float offsets, row stride 36 (32 + 4 pad)
#define A2H 0            // [128][36]
#define A2L 4608
#define A2M 9216
#define B2H 13824        // [96][36]
#define B2L 17280
#define B2M 20736
#define EPI_ 0           // overlay after mainloop: [128][100]
#define SMEMF 24192
#define SMEMSZ (SMEMF * 4)

__device__ __forceinline__ void loadA(const float* __restrict__ A, int Kdim,
                                      int m0, int k0, float4* Apre)
{
    #pragma unroll
    for (int j = 0; j < 4; j++) {
        int i = threadIdx.x + j * 256;
        int row = i >> 3;
        int gk = k0 + (i & 7) * 4;
        Apre[j] = (gk < Kdim) ? __ldg((const float4*)(A + (size_t)(m0 + row) * Kdim + gk))
                              : make_float4(0.f, 0.f, 0.f, 0.f);
    }
}
__device__ __forceinline__ void loadB(const float* __restrict__ W, int Kdim,
                                      int n0, int k0, float4* Bpre)
{
    #pragma unroll
    for (int j = 0; j < 3; j++) {
        int i = threadIdx.x + j * 256;
        int row = i >> 3;
        int gk = k0 + (i & 7) * 4;
        Bpre[j] = (gk < Kdim) ? __ldg((const float4*)(W + (size_t)(n0 + row) * Kdim + gk))
                              : make_float4(0.f, 0.f, 0.f, 0.f);
    }
}

__device__ __forceinline__ void split_sts(float* sm, int baseH, int baseL, int baseM,
                                          int o, float4 v)
{
    float4 h, l, mm;
    h.x = t32(v.x); h.y = t32(v.y); h.z = t32(v.z); h.w = t32(v.w);
    float rx = v.x - h.x, ry = v.y - h.y, rz = v.z - h.z, rw = v.w - h.w;
    l.x = t32(rx); l.y = t32(ry); l.z = t32(rz); l.w = t32(rw);
    mm.x = rx - l.x; mm.y = ry - l.y; mm.z = rz - l.z; mm.w = rw - l.w;
    *(float4*)&sm[baseH + o] = h;
    *(float4*)&sm[baseL + o] = l;
    *(float4*)&sm[baseM + o] = mm;
}

// mode 0: write C (row stride G3_) + bias
// mode 1: fused GRU step (gh + gates -> hout/seq)
__global__ __launch_bounds__(256, 1)
void mma_gemm(const float* __restrict__ A, const float* __restrict__ W,
              const float* __restrict__ bias,
              float* __restrict__ C,
              const float* __restrict__ xp, const float* __restrict__ hin,
              float* __restrict__ hout, float* __restrict__ seqp,
              int Kdim, int t, int mode)
{
    extern __shared__ __align__(16) float sm[];
    uint32_t* smu = (uint32_t*)sm;

    const int tid = threadIdx.x;
    const int wid = tid >> 5, lane = tid & 31;
    const int gid = lane >> 2, tig = lane & 3;
    const int wm = (wid >> 2) * 64;          // warp m offset (0 or 64)
    const int wn = (wid & 3) * 24;           // warp n offset (0,24,48,72)
    const int m0 = blockIdx.y * TM, n0 = blockIdx.x * TN;

    float master[4][3][4];
    #pragma unroll
    for (int i = 0; i < 4; i++)
        #pragma unroll
        for (int j = 0; j < 3; j++)
            #pragma unroll
            for (int q = 0; q < 4; q++) master[i][j][q] = 0.f;

    float4 Apre[4], Bpre[3];
    const int ntiles = (Kdim + KT - 1) / KT;
    loadA(A, Kdim, m0, 0, Apre);
    loadB(W, Kdim, n0, 0, Bpre);

    for (int kt = 0; kt < ntiles; kt++) {
        // --- STS with exact 3-way tf32 split ---
        #pragma unroll
        for (int j = 0; j < 4; j++) {
            int i = tid + j * 256;
            int o = (i >> 3) * 36 + (i & 7) * 4;
            split_sts(sm, A2H, A2L, A2M, o, Apre[j]);
        }
        #pragma unroll
        for (int j = 0; j < 3; j++) {
            int i = tid + j * 256;
            int o = (i >> 3) * 36 + (i & 7) * 4;
            split_sts(sm, B2H, B2L, B2M, o, Bpre[j]);
        }
        __syncthreads();

        if (kt + 1 < ntiles) {
            loadA(A, Kdim, m0, (kt + 1) * KT, Apre);
            loadB(W, Kdim, n0, (kt + 1) * KT, Bpre);
        }

        // --- fresh per-tile accumulator ---
        float acc[4][3][4];
        #pragma unroll
        for (int i = 0; i < 4; i++)
            #pragma unroll
            for (int j = 0; j < 3; j++)
                #pragma unroll
                for (int q = 0; q < 4; q++) acc[i][j][q] = 0.f;

        #pragma unroll
        for (int ks = 0; ks < KT; ks += 8) {
            uint32_t bh[3][2], bl[3][2], bm[3][2];
            #pragma unroll
            for (int f = 0; f < 3; f++) {
                int r0 = (wn + 8 * f + gid) * 36 + ks + tig;
                bh[f][0] = smu[B2H + r0]; bh[f][1] = smu[B2H + r0 + 4];
                bl[f][0] = smu[B2L + r0]; bl[f][1] = smu[B2L + r0 + 4];
                bm[f][0] = smu[B2M + r0]; bm[f][1] = smu[B2M + r0 + 4];
            }
            #pragma unroll
            for (int fm = 0; fm < 4; fm++) {
                uint32_t ah[4], al[4], am_[4];
                int r0 = (wm + 16 * fm + gid) * 36 + ks + tig;
                ah[0] = smu[A2H + r0]; ah[1] = smu[A2H + r0 + 288];
                ah[2] = smu[A2H + r0 + 4]; ah[3] = smu[A2H + r0 + 292];
                al[0] = smu[A2L + r0]; al[1] = smu[A2L + r0 + 288];
                al[2] = smu[A2L + r0 + 4]; al[3] = smu[A2L + r0 + 292];
                am_[0] = smu[A2M + r0]; am_[1] = smu[A2M + r0 + 288];
                am_[2] = smu[A2M + r0 + 4]; am_[3] = smu[A2M + r0 + 292];
                #pragma unroll
                for (int fn = 0; fn < 3; fn++) {
                    mma8(acc[fm][fn], ah, bh[fn]);
                    mma8(acc[fm][fn], ah, bl[fn]);
                    mma8(acc[fm][fn], al, bh[fn]);
                    mma8(acc[fm][fn], al, bl[fn]);
                    mma8(acc[fm][fn], ah, bm[fn]);
                    mma8(acc[fm][fn], am_, bh[fn]);
                }
            }
        }

        // --- fold tile into master with RN adds ---
        #pragma unroll
        for (int i = 0; i < 4; i++)
            #pragma unroll
            for (int j = 0; j < 3; j++)
                #pragma unroll
                for (int q = 0; q < 4; q++) master[i][j][q] += acc[i][j][q];

        __syncthreads();
    }

    // --- write fragments to SMEM epilogue tile [128][100] ---
    #pragma unroll
    for (int fm = 0; fm < 4; fm++) {
        int row = wm + 16 * fm + gid;
        #pragma unroll
        for (int fn = 0; fn < 3; fn++) {
            int col = wn + 8 * fn + 2 * tig;
            *(float2*)&sm[EPI_ + row * 100 + col] =
                make_float2(master[fm][fn][0], master[fm][fn][1]);
            *(float2*)&sm[EPI_ + (row + 8) * 100 + col] =
                make_float2(master[fm][fn][2], master[fm][fn][3]);
        }
    }
    __syncthreads();

    if (mode == 0) {
        int row = tid >> 1, half = tid & 1;
        int cb = half * 48;
        float* cp = C + (size_t)(m0 + row) * G3_ + n0 + cb;
        #pragma unroll
        for (int j = 0; j < 12; j++) {
            float4 v = *(float4*)&sm[EPI_ + row * 100 + cb + j * 4];
            float4 bb = *(const float4*)&bias[n0 + cb + j * 4];
            v.x += bb.x; v.y += bb.y; v.z += bb.z; v.w += bb.w;
            *(float4*)(cp + j * 4) = v;
        }
    } else {
        #pragma unroll
        for (int it = 0; it < 16; it++) {
            int unit = tid + it * 256;
            int u = unit & 31;          // triple index 0..31
            int row = unit >> 5;        // 0..127
            int b = m0 + row;
            int c0 = 3 * u;
            float gr = sm[EPI_ + row * 100 + c0]     + bias[n0 + c0];
            float gz = sm[EPI_ + row * 100 + c0 + 1] + bias[n0 + c0 + 1];
            float gn = sm[EPI_ + row * 100 + c0 + 2] + bias[n0 + c0 + 2];
            const float* xr = xp + ((size_t)b * T_ + t) * G3_ + n0 + c0;
            float r  = sigf(xr[0] + gr);
            float z  = sigf(xr[1] + gz);
            float nn = tanhf(xr[2] + r * gn);
            int hu = n0 / 3 + u;
            float hp = hin[(size_t)b * H_ + hu];
            float hv = (1.f - z) * nn + z * hp;
            hout[(size_t)b * H_ + hu] = hv;
            if (seqp) seqp[((size_t)b * T_ + t) * H_ + hu] = hv;
        }
    }
}

// ===================== FFMA2 GEMM (head only) =====================
#define BM 128
#define BN 96
#define BK 16
#define NT 256

__device__ __forceinline__ ull pack2(float lo, float hi) {
    ull r; asm("mov.b64 %0, {%1, %2};" : "=l"(r) : "f"(lo), "f"(hi)); return r;
}
__device__ __forceinline__ float2 unpack2(ull v) {
    float2 r; asm("mov.b64 {%0, %1}, %2;" : "=f"(r.x), "=f"(r.y) : "l"(v)); return r;
}
__device__ __forceinline__ void ffma2(ull& d, ull a, ull b) {
    asm("fma.rn.f32x2 %0, %1, %2, %3;" : "=l"(d) : "l"(a), "l"(b), "l"(d));
}

__device__ __forceinline__ void load_tileA(const float* __restrict__ A, int M, int K,
                                           int m0, int k0, int am, int ak, float4* Apre)
{
    #pragma unroll
    for (int r = 0; r < 2; r++) {
        int gm = m0 + am + r * 64;
        int gk = k0 + ak;
        float4 v = make_float4(0.f, 0.f, 0.f, 0.f);
        if (gm < M) {
            if (gk + 3 < K) v = *(const float4*)(A + (size_t)gm * K + gk);
            else {
                if (gk + 0 < K) v.x = A[(size_t)gm * K + gk + 0];
                if (gk + 1 < K) v.y = A[(size_t)gm * K + gk + 1];
                if (gk + 2 < K) v.z = A[(size_t)gm * K + gk + 2];
                if (gk + 3 < K) v.w = A[(size_t)gm * K + gk + 3];
            }
        }
        Apre[r] = v;
    }
}
__device__ __forceinline__ void load_tileB(const float* __restrict__ Bm, int Nd, int K,
                                           int n0, int k0, int tid, float2* Bpre)
{
    #pragma unroll
    for (int j = 0; j < 3; j++) {
        int i2 = tid + j * 256;
        int bn = i2 >> 3;
        int bk = (i2 & 7) << 1;
        int gn = n0 + bn, gk = k0 + bk;
        float2 v = make_float2(0.f, 0.f);
        if (gn < Nd && gk < K) v = *(const float2*)(Bm + (size_t)gn * K + gk);
        Bpre[j] = v;
    }
}

__global__ __launch_bounds__(NT)
void gemm_f2(const float* __restrict__ A, const float* __restrict__ Bm,
             const float* __restrict__ bias, float* __restrict__ C,
             int M, int Nd, int K)
{
    __shared__ float As[BK][BM + 4];
    __shared__ float Bs[BK][BN + 2];
    const int tid = threadIdx.x;
    const int tx = tid & 15, ty = tid >> 4;
    const int m0 = blockIdx.y * BM, n0 = blockIdx.x * BN;
    const int am = tid >> 2;
    const int ak = (tid & 3) << 2;
    ull acc[4][6];
    #pragma unroll
    for (int i = 0; i < 4; i++)
        #pragma unroll
        for (int j = 0; j < 6; j++) acc[i][j] = 0ull;
    float4 Apre[2]; float2 Bpre[3];
    const int ntiles = (K + BK - 1) / BK;
    load_tileA(A, M, K, m0, 0, am, ak, Apre);
    load_tileB(Bm, Nd, K, n0, 0, tid, Bpre);
    for (int kt = 0; kt < ntiles; kt++) {
        #pragma unroll
        for (int r = 0; r < 2; r++) {
            As[ak + 0][am + r * 64] = Apre[r].x;
            As[ak + 1][am + r * 64] = Apre[r].y;
            As[ak + 2][am + r * 64] = Apre[r].z;
            As[ak + 3][am + r * 64] = Apre[r].w;
        }
        #pragma unroll
        for (int j = 0; j < 3; j++) {
            int i2 = tid + j * 256;
            int bn = i2 >> 3, bk = (i2 & 7) << 1;
            Bs[bk][bn]     = Bpre[j].x;
            Bs[bk + 1][bn] = Bpre[j].y;
        }
        __syncthreads();
        if (kt + 1 < ntiles) {
            load_tileA(A, M, K, m0, (kt + 1) * BK, am, ak, Apre);
            load_tileB(Bm, Nd, K, n0, (kt + 1) * BK, tid, Bpre);
        }
        #pragma unroll
        for (int k = 0; k < BK; k++) {
            ull av[4];
            #pragma unroll
            for (int i = 0; i < 4; i++) av[i] = *(const ull*)&As[k][ty * 8 + 2 * i];
            ull bv[6];
            #pragma unroll
            for (int j = 0; j < 6; j++) { float b = Bs[k][tx * 6 + j]; bv[j] = pack2(b, b); }
            #pragma unroll
            for (int i = 0; i < 4; i++)
                #pragma unroll
                for (int j = 0; j < 6; j++) ffma2(acc[i][j], av[i], bv[j]);
        }
        __syncthreads();
    }
    #pragma unroll
    for (int i = 0; i < 4; i++) {
        int gm0 = m0 + ty * 8 + 2 * i;
        #pragma unroll
        for (int j = 0; j < 6; j++) {
            int gn = n0 + tx * 6 + j;
            if (gn >= Nd) continue;
            float2 v = unpack2(acc[i][j]);
            float bb = bias ? bias[gn] : 0.f;
            if (gm0 < M)     C[(size_t)gm0 * Nd + gn]       = v.x + bb;
            if (gm0 + 1 < M) C[(size_t)(gm0 + 1) * Nd + gn] = v.y + bb;
        }
    }
}

// ===================== misc kernels =====================
__global__ void permute_w(const float* __restrict__ w, float* __restrict__ wp, int K)
{
    int c = blockIdx.y;
    int k = blockIdx.x * 256 + threadIdx.x;
    if (k >= K) return;
    int g = c % 3, h = c / 3;
    wp[(size_t)c * K + k] = w[(size_t)(g * H_ + h) * K + k];
}
__global__ void permute_b(const float* __restrict__ b, float* __restrict__ bp)
{
    int c = blockIdx.x * 256 + threadIdx.x;
    if (c < G3_) bp[c] = b[(c % 3) * H_ + c / 3];
}
__global__ void zero_kernel(float* __restrict__ p, int n)
{
    int i = blockIdx.x * blockDim.x + threadIdx.x;
    if (i < n) p[i] = 0.f;
}

__global__ __launch_bounds__(256)
void ln_silu(const float* __restrict__ z,
             const float* __restrict__ lng,
             const float* __restrict__ lnb,
             float* __restrict__ out)
{
    __shared__ float red[256];
    int b = blockIdx.x, tid = threadIdx.x;
    const float* row = z + (size_t)b * H_;
    float s = 0.f, s2 = 0.f;
    for (int i = tid; i < H_; i += 256) { float v = row[i]; s += v; s2 += v * v; }
    red[tid] = s; __syncthreads();
    for (int o = 128; o > 0; o >>= 1) { if (tid < o) red[tid] += red[tid + o]; __syncthreads(); }
    float mu = red[0] / H_;
    __syncthreads();
    red[tid] = s2; __syncthreads();
    for (int o = 128; o > 0; o >>= 1) { if (tid < o) red[tid] += red[tid + o]; __syncthreads(); }
    float var = red[0] / H_ - mu * mu;
    float inv = rsqrtf(var + 1e-5f);
    for (int i = tid; i < H_; i += 256) {
        float y = (row[i] - mu) * inv * lng[i] + lnb[i];
        out[(size_t)b * H_ + i] = y / (1.f + expf(-y));
    }
}

__global__ __launch_bounds__(512)
void softmax_rebalance(const float* __restrict__ scores,
                       float* __restrict__ out)
{
    __shared__ float red[512];
    int b = blockIdx.x, tid = threadIdx.x;
    float s = (tid < N_) ? scores[(size_t)b * N_ + tid] : -INFINITY;
    if (s < 0.f) s = -INFINITY;
    red[tid] = s; __syncthreads();
    for (int o = 256; o > 0; o >>= 1) { if (tid < o) red[tid] = fmaxf(red[tid], red[tid + o]); __syncthreads(); }
    float m = red[0]; __syncthreads();
    float e = (tid < N_) ? expf(s - m) : 0.f;
    red[tid] = e; __syncthreads();
    for (int o = 256; o > 0; o >>= 1) { if (tid < o) red[tid] += red[tid + o]; __syncthreads(); }
    float S = red[0]; __syncthreads();
    float w = e / S;
    w = fminf(fmaxf(w, 0.0f), 0.1f);
    for (int it = 0; it < 20; it++) {
        red[tid] = (tid < N_) ? w : 0.f; __syncthreads();
        for (int o = 256; o > 0; o >>= 1) { if (tid < o) red[tid] += red[tid + o]; __syncthreads(); }
        float tot = red[0]; __syncthreads();
        float excess = tot - 1.0f;
        bool  active = excess > 1e-6f;
        float sur = fmaxf(w - 0.1f, 0.f);
        red[tid] = (tid < N_) ? sur : 0.f; __syncthreads();
        for (int o = 256; o > 0; o >>= 1) { if (tid < o) red[tid] += red[tid + o]; __syncthreads(); }
        float totsur = red[0]; __syncthreads();
        float upd = (totsur > 0.f)
                  ? w - sur / fmaxf(totsur, 1e-12f) * excess
                  : w - excess / (float)N_;
        upd = fminf(fmaxf(upd, 0.0f), 0.1f);
        if (active) w = upd;
    }
    if (tid < N_) out[(size_t)b * N_ + tid] = w;
}

// ===================== orchestration =====================
extern "C" void kernel_launch(void* const* d_in, const int* in_sizes, int n_in,
                              void* d_out, int out_size)
{
    const float* x     = (const float*)d_in[0];
    const float* w_ih0 = (const float*)d_in[1];
    const float* w_hh0 = (const float*)d_in[2];
    const float* b_ih0 = (const float*)d_in[3];
    const float* b_hh0 = (const float*)d_in[4];
    const float* w_ih1 = (const float*)d_in[5];
    const float* w_hh1 = (const float*)d_in[6];
    const float* b_ih1 = (const float*)d_in[7];
    const float* b_hh1 = (const float*)d_in[8];
    const float* w1    = (const float*)d_in[9];
    const float* b1    = (const float*)d_in[10];
    const float* ln_g  = (const float*)d_in[11];
    const float* ln_b  = (const float*)d_in[12];
    const float* w2    = (const float*)d_in[13];
    const float* b2    = (const float*)d_in[14];
    float* out = (float*)d_out;

    void* p;
    float *xproj, *seq, *h0, *h1, *z, *za, *scores;
    float *wih0p, *whh0p, *wih1p, *whh1p, *bih0p, *bhh0p, *bih1p, *bhh1p;
    cudaGetSymbolAddress(&p, g_xproj);  xproj  = (float*)p;
    cudaGetSymbolAddress(&p, g_seq);    seq    = (float*)p;
    cudaGetSymbolAddress(&p, g_h0);     h0     = (float*)p;
    cudaGetSymbolAddress(&p, g_h1);     h1     = (float*)p;
    cudaGetSymbolAddress(&p, g_z);      z      = (float*)p;
    cudaGetSymbolAddress(&p, g_za);     za     = (float*)p;
    cudaGetSymbolAddress(&p, g_scores); scores = (float*)p;
    cudaGetSymbolAddress(&p, g_wih0p);  wih0p  = (float*)p;
    cudaGetSymbolAddress(&p, g_whh0p);  whh0p  = (float*)p;
    cudaGetSymbolAddress(&p, g_wih1p);  wih1p  = (float*)p;
    cudaGetSymbolAddress(&p, g_whh1p);  whh1p  = (float*)p;
    cudaGetSymbolAddress(&p, g_bih0p);  bih0p  = (float*)p;
    cudaGetSymbolAddress(&p, g_bhh0p);  bhh0p  = (float*)p;
    cudaGetSymbolAddress(&p, g_bih1p);  bih1p  = (float*)p;
    cudaGetSymbolAddress(&p, g_bhh1p);  bhh1p  = (float*)p;

    cudaFuncSetAttribute(mma_gemm, cudaFuncAttributeMaxDynamicSharedMemorySize, SMEMSZ);

    // permute weights/biases into gate-interleaved layout (h*3+g)
    permute_w<<<dim3((N_ + 255) / 256, G3_), 256>>>(w_ih0, wih0p, N_);
    permute_w<<<dim3((H_ + 255) / 256, G3_), 256>>>(w_hh0, whh0p, H_);
    permute_w<<<dim3((H_ + 255) / 256, G3_), 256>>>(w_ih1, wih1p, H_);
    permute_w<<<dim3((H_ + 255) / 256, G3_), 256>>>(w_hh1, whh1p, H_);
    permute_b<<<(G3_ + 255) / 256, 256>>>(b_ih0, bih0p);
    permute_b<<<(G3_ + 255) / 256, 256>>>(b_hh0, bhh0p);
    permute_b<<<(G3_ + 255) / 256, 256>>>(b_ih1, bih1p);
    permute_b<<<(G3_ + 255) / 256, 256>>>(b_hh1, bhh1p);

    // layer 0 input projection
    mma_gemm<<<dim3(G3_ / TN, BT_ / TM), 256, SMEMSZ>>>(
        x, wih0p, bih0p, xproj, nullptr, nullptr, nullptr, nullptr, N_, 0, 0);
    zero_kernel<<<(B_ * H_ + 255) / 256, 256>>>(h0, B_ * H_);

    // layer 0 recurrence (fused GEMM + gates)
    for (int t = 0; t < T_; t++) {
        float* hin  = (t & 1) ? h1 : h0;
        float* hout = (t & 1) ? h0 : h1;
        mma_gemm<<<dim3(G3_ / TN, B_ / TM), 256, SMEMSZ>>>(
            hin, whh0p, bhh0p, nullptr, xproj, hin, hout, seq, H_, t, 1);
    }

    // layer 1 input projection
    mma_gemm<<<dim3(G3_ / TN, BT_ / TM), 256, SMEMSZ>>>(
        seq, wih1p, bih1p, xproj, nullptr, nullptr, nullptr, nullptr, H_, 0, 0);
    zero_kernel<<<(B_ * H_ + 255) / 256, 256>>>(h0, B_ * H_);

    // layer 1 recurrence
    for (int t = 0; t < T_; t++) {
        float* hin  = (t & 1) ? h1 : h0;
        float* hout = (t & 1) ? h0 : h1;
        mma_gemm<<<dim3(G3_ / TN, B_ / TM), 256, SMEMSZ>>>(
            hin, whh1p, bhh1p, nullptr, xproj, hin, hout, nullptr, H_, t, 1);
    }

    // head (FFMA2 path; tiny)
    gemm_f2<<<dim3((H_ + BN - 1) / BN, B_ / BM), NT>>>(h0, w1, b1, z, B_, H_, H_);
    ln_silu<<<B_, 256>>>(z, ln_g, ln_b, za);
    gemm_f2<<<dim3((N_ + BN - 1) / BN, B_ / BM), NT>>>(za, w2, b2, scores, B_, N_, H_);
    softmax_rebalance<<<B_, 512>>>(scores, out);
}

// round 8
// speedup vs baseline: 1.0546x; 1.0542x over previous
#include <cuda_runtime.h>
#include <math.h>
#include <stdint.h>

#define B_   512
#define T_   128
#define N_   500
#define H_   1024
#define G3_  3072
#define BT_  65536

typedef unsigned long long ull;

// ===================== static device scratch =====================
__device__ float g_xproj[(size_t)BT_ * G3_];
__device__ float g_seq  [(size_t)BT_ * H_];
__device__ float g_h0   [B_ * H_];
__device__ float g_h1   [B_ * H_];
__device__ float g_z    [B_ * H_];
__device__ float g_za   [B_ * H_];
__device__ float g_scores[B_ * N_];
__device__ float g_wih0p[(size_t)G3_ * N_];
__device__ float g_whh0p[(size_t)G3_ * H_];
__device__ float g_wih1p[(size_t)G3_ * H_];
__device__ float g_whh1p[(size_t)G3_ * H_];
__device__ float g_bih0p[G3_];
__device__ float g_bhh0p[G3_];
__device__ float g_bih1p[G3_];
__device__ float g_bhh1p[G3_];

// ===================== helpers =====================
__device__ __forceinline__ void ffma2(ull& d, ull a, ull b) {
    asm("fma.rn.f32x2 %0, %1, %2, %3;" : "=l"(d) : "l"(a), "l"(b), "l"(d));
}
__device__ __forceinline__ float2 unpack2(ull v) {
    float2 r; asm("mov.b64 {%0, %1}, %2;" : "=f"(r.x), "=f"(r.y) : "l"(v)); return r;
}
__device__ __forceinline__ float sigf(float x) { return 1.f / (1.f + __expf(-x)); }

__device__ __forceinline__ void cpa16(uint32_t d, const void* s, int sz) {
    asm volatile("cp.async.cg.shared.global [%0], [%1], 16, %2;"
                 :: "r"(d), "l"(s), "r"(sz));
}
__device__ __forceinline__ void cpa8(uint32_t d, const void* s, int sz) {
    asm volatile("cp.async.ca.shared.global [%0], [%1], 8, %2;"
                 :: "r"(d), "l"(s), "r"(sz));
}
#define CP_COMMIT() asm volatile("cp.async.commit_group;" ::: "memory")
#define CP_WAIT1()  asm volatile("cp.async.wait_group 1;" ::: "memory")

// ===================== k-pair FFMA2 GEMM with cp.async pipeline =====================
// C[M x Nd] = A[M x K] @ W[Nd x K]^T (+bias). Thread tile 8 rows x 6 cols,
// cols n = n0 + tx + 16*j. acc(m,n) packs (even-k sum, odd-k sum) in one f32x2.
#define BM 128
#define BN 96
#define BK 16
#define AS_STRIDE 20
#define BS_STRIDE 18
#define AS_F (BM * AS_STRIDE)       // 2560 floats
#define BS_F (BN * BS_STRIDE)       // 1728 floats
#define STG_F (AS_F + BS_F)         // 4288 floats per stage
#define SMEMF 12960                 // >= max(3*4288=12864, 128*100=12800)
#define SMEMSZ (SMEMF * 4)

__device__ __forceinline__ void issue_tile(const float* __restrict__ A,
                                           const float* __restrict__ W,
                                           int Nd, int K, int m0, int n0, int k0,
                                           uint32_t sbase, int tid)
{
    int am = tid >> 2, ak = (tid & 3) << 2;
    #pragma unroll
    for (int r = 0; r < 2; r++) {
        int gm = m0 + am + r * 64, gk = k0 + ak;
        uint32_t d = sbase + (uint32_t)(((am + r * 64) * AS_STRIDE + ak) * 4);
        int rem = K - gk;
        int sz = (rem >= 4) ? 16 : ((rem > 0) ? rem * 4 : 0);
        const float* s = A + (size_t)gm * K + (gk < K ? gk : 0);
        cpa16(d, s, sz);
    }
    #pragma unroll
    for (int j = 0; j < 3; j++) {
        int i2 = tid + j * 256;
        int bn = i2 >> 3, bk = (i2 & 7) << 1;
        int gn = n0 + bn, gk = k0 + bk;
        uint32_t d = sbase + (uint32_t)((AS_F + bn * BS_STRIDE + bk) * 4);
        int sz = (gn < Nd && gk + 2 <= K) ? 8 : 0;   // K always even
        const float* s = W + (size_t)(gn < Nd ? gn : 0) * K + (gk + 2 <= K ? gk : 0);
        cpa8(d, s, sz);
    }
}

// mode 0: C[gm*ldC+gn] = sum + bias ; mode 1: fused GRU gates -> hout/seq
__global__ __launch_bounds__(256)
void gemm_ca(const float* __restrict__ A, const float* __restrict__ W,
             const float* __restrict__ bias,
             float* __restrict__ C, int ldC,
             const float* __restrict__ xp, const float* __restrict__ hin,
             float* __restrict__ hout, float* __restrict__ seqp,
             int Nd, int K, int t, int mode)
{
    extern __shared__ __align__(16) float sm[];
    const int tid = threadIdx.x;
    const int tx = tid & 15, ty = tid >> 4;
    const int m0 = blockIdx.y * BM, n0 = blockIdx.x * BN;

    uint32_t sb;
    asm("{ .reg .u64 tt; cvta.to.shared.u64 tt, %1; cvt.u32.u64 %0, tt; }"
        : "=r"(sb) : "l"(sm));

    ull acc[8][6];
    #pragma unroll
    for (int i = 0; i < 8; i++)
        #pragma unroll
        for (int j = 0; j < 6; j++) acc[i][j] = 0ull;

    const int nt = (K + BK - 1) / BK;
    issue_tile(A, W, Nd, K, m0, n0, 0,      sb,                         tid); CP_COMMIT();
    issue_tile(A, W, Nd, K, m0, n0, BK,     sb + (uint32_t)(STG_F * 4), tid); CP_COMMIT();

    for (int kt = 0; kt < nt; kt++) {
        CP_WAIT1();
        __syncthreads();
        if (kt + 2 < nt)
            issue_tile(A, W, Nd, K, m0, n0, (kt + 2) * BK,
                       sb + (uint32_t)(((kt + 2) % 3) * STG_F * 4), tid);
        CP_COMMIT();

        const float* sA = sm + (kt % 3) * STG_F;
        const float* sB = sA + AS_F;
        #pragma unroll
        for (int kp = 0; kp < 8; kp++) {
            ull bv[6];
            #pragma unroll
            for (int j = 0; j < 6; j++)
                bv[j] = *(const ull*)&sB[(tx + 16 * j) * BS_STRIDE + 2 * kp];
            #pragma unroll
            for (int i = 0; i < 8; i++) {
                ull av = *(const ull*)&sA[(ty * 8 + i) * AS_STRIDE + 2 * kp];
                #pragma unroll
                for (int j = 0; j < 6; j++) ffma2(acc[i][j], av, bv[j]);
            }
        }
    }

    if (mode == 0) {
        #pragma unroll
        for (int i = 0; i < 8; i++) {
            int gm = m0 + ty * 8 + i;
            #pragma unroll
            for (int j = 0; j < 6; j++) {
                int gn = n0 + tx + 16 * j;
                if (gn < Nd) {
                    float2 v = unpack2(acc[i][j]);
                    C[(size_t)gm * ldC + gn] = v.x + v.y + bias[gn];
                }
            }
        }
    } else {
        // overlay epilogue tile [128][100] over the pipeline stages
        __syncthreads();
        #pragma unroll
        for (int i = 0; i < 8; i++) {
            int row = ty * 8 + i;
            #pragma unroll
            for (int j = 0; j < 6; j++) {
                float2 v = unpack2(acc[i][j]);
                sm[row * 100 + tx + 16 * j] = v.x + v.y;
            }
        }
        __syncthreads();
        #pragma unroll
        for (int it = 0; it < 16; it++) {
            int unit = tid + it * 256;
            int u = unit & 31;           // triple index 0..31
            int row = unit >> 5;         // 0..127
            int b = m0 + row;
            int c0 = 3 * u;
            float gr = sm[row * 100 + c0]     + bias[n0 + c0];
            float gz = sm[row * 100 + c0 + 1] + bias[n0 + c0 + 1];
            float gn = sm[row * 100 + c0 + 2] + bias[n0 + c0 + 2];
            const float* xr = xp + ((size_t)b * T_ + t) * G3_ + n0 + c0;
            float r  = sigf(xr[0] + gr);
            float z  = sigf(xr[1] + gz);
            float nn = tanhf(xr[2] + r * gn);
            int hu = n0 / 3 + u;
            float hp = hin[(size_t)b * H_ + hu];
            float hv = (1.f - z) * nn + z * hp;
            hout[(size_t)b * H_ + hu] = hv;
            if (seqp) seqp[((size_t)b * T_ + t) * H_ + hu] = hv;
        }
    }
}

// ===================== misc kernels =====================
__global__ void permute_w(const float* __restrict__ w, float* __restrict__ wp, int K)
{
    int c = blockIdx.y;
    int k = blockIdx.x * 256 + threadIdx.x;
    if (k >= K) return;
    int g = c % 3, h = c / 3;
    wp[(size_t)c * K + k] = w[(size_t)(g * H_ + h) * K + k];
}
__global__ void permute_b(const float* __restrict__ b, float* __restrict__ bp)
{
    int c = blockIdx.x * 256 + threadIdx.x;
    if (c < G3_) bp[c] = b[(c % 3) * H_ + c / 3];
}
__global__ void zero_kernel(float* __restrict__ p, int n)
{
    int i = blockIdx.x * blockDim.x + threadIdx.x;
    if (i < n) p[i] = 0.f;
}

__global__ __launch_bounds__(256)
void ln_silu(const float* __restrict__ z,
             const float* __restrict__ lng,
             const float* __restrict__ lnb,
             float* __restrict__ out)
{
    __shared__ float red[256];
    int b = blockIdx.x, tid = threadIdx.x;
    const float* row = z + (size_t)b * H_;
    float s = 0.f, s2 = 0.f;
    for (int i = tid; i < H_; i += 256) { float v = row[i]; s += v; s2 += v * v; }
    red[tid] = s; __syncthreads();
    for (int o = 128; o > 0; o >>= 1) { if (tid < o) red[tid] += red[tid + o]; __syncthreads(); }
    float mu = red[0] / H_;
    __syncthreads();
    red[tid] = s2; __syncthreads();
    for (int o = 128; o > 0; o >>= 1) { if (tid < o) red[tid] += red[tid + o]; __syncthreads(); }
    float var = red[0] / H_ - mu * mu;
    float inv = rsqrtf(var + 1e-5f);
    for (int i = tid; i < H_; i += 256) {
        float y = (row[i] - mu) * inv * lng[i] + lnb[i];
        out[(size_t)b * H_ + i] = y / (1.f + expf(-y));
    }
}

__global__ __launch_bounds__(512)
void softmax_rebalance(const float* __restrict__ scores,
                       float* __restrict__ out)
{
    __shared__ float red[512];
    int b = blockIdx.x, tid = threadIdx.x;
    float s = (tid < N_) ? scores[(size_t)b * N_ + tid] : -INFINITY;
    if (s < 0.f) s = -INFINITY;
    red[tid] = s; __syncthreads();
    for (int o = 256; o > 0; o >>= 1) { if (tid < o) red[tid] = fmaxf(red[tid], red[tid + o]); __syncthreads(); }
    float m = red[0]; __syncthreads();
    float e = (tid < N_) ? expf(s - m) : 0.f;
    red[tid] = e; __syncthreads();
    for (int o = 256; o > 0; o >>= 1) { if (tid < o) red[tid] += red[tid + o]; __syncthreads(); }
    float S = red[0]; __syncthreads();
    float w = e / S;
    w = fminf(fmaxf(w, 0.0f), 0.1f);
    for (int it = 0; it < 20; it++) {
        red[tid] = (tid < N_) ? w : 0.f; __syncthreads();
        for (int o = 256; o > 0; o >>= 1) { if (tid < o) red[tid] += red[tid + o]; __syncthreads(); }
        float tot = red[0]; __syncthreads();
        float excess = tot - 1.0f;
        bool  active = excess > 1e-6f;
        float sur = fmaxf(w - 0.1f, 0.f);
        red[tid] = (tid < N_) ? sur : 0.f; __syncthreads();
        for (int o = 256; o > 0; o >>= 1) { if (tid < o) red[tid] += red[tid + o]; __syncthreads(); }
        float totsur = red[0]; __syncthreads();
        float upd = (totsur > 0.f)
                  ? w - sur / fmaxf(totsur, 1e-12f) * excess
                  : w - excess / (float)N_;
        upd = fminf(fmaxf(upd, 0.0f), 0.1f);
        if (active) w = upd;
    }
    if (tid < N_) out[(size_t)b * N_ + tid] = w;
}

// ===================== orchestration =====================
extern "C" void kernel_launch(void* const* d_in, const int* in_sizes, int n_in,
                              void* d_out, int out_size)
{
    const float* x     = (const float*)d_in[0];
    const float* w_ih0 = (const float*)d_in[1];
    const float* w_hh0 = (const float*)d_in[2];
    const float* b_ih0 = (const float*)d_in[3];
    const float* b_hh0 = (const float*)d_in[4];
    const float* w_ih1 = (const float*)d_in[5];
    const float* w_hh1 = (const float*)d_in[6];
    const float* b_ih1 = (const float*)d_in[7];
    const float* b_hh1 = (const float*)d_in[8];
    const float* w1    = (const float*)d_in[9];
    const float* b1    = (const float*)d_in[10];
    const float* ln_g  = (const float*)d_in[11];
    const float* ln_b  = (const float*)d_in[12];
    const float* w2    = (const float*)d_in[13];
    const float* b2    = (const float*)d_in[14];
    float* out = (float*)d_out;

    void* p;
    float *xproj, *seq, *h0, *h1, *z, *za, *scores;
    float *wih0p, *whh0p, *wih1p, *whh1p, *bih0p, *bhh0p, *bih1p, *bhh1p;
    cudaGetSymbolAddress(&p, g_xproj);  xproj  = (float*)p;
    cudaGetSymbolAddress(&p, g_seq);    seq    = (float*)p;
    cudaGetSymbolAddress(&p, g_h0);     h0     = (float*)p;
    cudaGetSymbolAddress(&p, g_h1);     h1     = (float*)p;
    cudaGetSymbolAddress(&p, g_z);      z      = (float*)p;
    cudaGetSymbolAddress(&p, g_za);     za     = (float*)p;
    cudaGetSymbolAddress(&p, g_scores); scores = (float*)p;
    cudaGetSymbolAddress(&p, g_wih0p);  wih0p  = (float*)p;
    cudaGetSymbolAddress(&p, g_whh0p);  whh0p  = (float*)p;
    cudaGetSymbolAddress(&p, g_wih1p);  wih1p  = (float*)p;
    cudaGetSymbolAddress(&p, g_whh1p);  whh1p  = (float*)p;
    cudaGetSymbolAddress(&p, g_bih0p);  bih0p  = (float*)p;
    cudaGetSymbolAddress(&p, g_bhh0p);  bhh0p  = (float*)p;
    cudaGetSymbolAddress(&p, g_bih1p);  bih1p  = (float*)p;
    cudaGetSymbolAddress(&p, g_bhh1p);  bhh1p  = (float*)p;

    cudaFuncSetAttribute(gemm_ca, cudaFuncAttributeMaxDynamicSharedMemorySize, SMEMSZ);

    // permute weights/biases into gate-interleaved layout (h*3+g)
    permute_w<<<dim3((N_ + 255) / 256, G3_), 256>>>(w_ih0, wih0p, N_);
    permute_w<<<dim3((H_ + 255) / 256, G3_), 256>>>(w_hh0, whh0p, H_);
    permute_w<<<dim3((H_ + 255) / 256, G3_), 256>>>(w_ih1, wih1p, H_);
    permute_w<<<dim3((H_ + 255) / 256, G3_), 256>>>(w_hh1, whh1p, H_);
    permute_b<<<(G3_ + 255) / 256, 256>>>(b_ih0, bih0p);
    permute_b<<<(G3_ + 255) / 256, 256>>>(b_hh0, bhh0p);
    permute_b<<<(G3_ + 255) / 256, 256>>>(b_ih1, bih1p);
    permute_b<<<(G3_ + 255) / 256, 256>>>(b_hh1, bhh1p);

    // layer 0 input projection: xproj = x @ wih0p^T + bih0p
    gemm_ca<<<dim3(G3_ / BN, BT_ / BM), 256, SMEMSZ>>>(
        x, wih0p, bih0p, xproj, G3_, nullptr, nullptr, nullptr, nullptr, G3_, N_, 0, 0);
    zero_kernel<<<(B_ * H_ + 255) / 256, 256>>>(h0, B_ * H_);

    // layer 0 recurrence (fused GEMM + gates)
    for (int t = 0; t < T_; t++) {
        float* hin  = (t & 1) ? h1 : h0;
        float* hout = (t & 1) ? h0 : h1;
        gemm_ca<<<dim3(G3_ / BN, B_ / BM), 256, SMEMSZ>>>(
            hin, whh0p, bhh0p, nullptr, 0, xproj, hin, hout, seq, G3_, H_, t, 1);
    }

    // layer 1 input projection
    gemm_ca<<<dim3(G3_ / BN, BT_ / BM), 256, SMEMSZ>>>(
        seq, wih1p, bih1p, xproj, G3_, nullptr, nullptr, nullptr, nullptr, G3_, H_, 0, 0);
    zero_kernel<<<(B_ * H_ + 255) / 256, 256>>>(h0, B_ * H_);

    // layer 1 recurrence
    for (int t = 0; t < T_; t++) {
        float* hin  = (t & 1) ? h1 : h0;
        float* hout = (t & 1) ? h0 : h1;
        gemm_ca<<<dim3(G3_ / BN, B_ / BM), 256, SMEMSZ>>>(
            hin, whh1p, bhh1p, nullptr, 0, xproj, hin, hout, nullptr, G3_, H_, t, 1);
    }

    // head
    gemm_ca<<<dim3((H_ + BN - 1) / BN, B_ / BM), 256, SMEMSZ>>>(
        h0, w1, b1, z, H_, nullptr, nullptr, nullptr, nullptr, H_, H_, 0, 0);
    ln_silu<<<B_, 256>>>(z, ln_g, ln_b, za);
    gemm_ca<<<dim3((N_ + BN - 1) / BN, B_ / BM), 256, SMEMSZ>>>(
        za, w2, b2, scores, N_, nullptr, nullptr, nullptr, nullptr, N_, H_, 0, 0);
    softmax_rebalance<<<B_, 512>>>(scores, out);
}

// round 9
// speedup vs baseline: 1.0958x; 1.0390x over previous
#include <cuda_runtime.h>
#include <math.h>
#include <stdint.h>

#define B_   512
#define T_   128
#define N_   500
#define H_   1024
#define G3_  3072
#define BT_  65536

typedef unsigned long long ull;

// ===================== static device scratch =====================
__device__ float g_xproj[(size_t)BT_ * G3_];
__device__ float g_seq  [(size_t)BT_ * H_];
__device__ float g_h0   [B_ * H_];
__device__ float g_h1   [B_ * H_];
__device__ float g_z    [B_ * H_];
__device__ float g_za   [B_ * H_];
__device__ float g_scores[B_ * N_];
__device__ float g_wih0p[(size_t)G3_ * N_];
__device__ float g_whh0p[(size_t)G3_ * H_];
__device__ float g_wih1p[(size_t)G3_ * H_];
__device__ float g_whh1p[(size_t)G3_ * H_];
__device__ float g_bih0p[G3_];
__device__ float g_bhh0p[G3_];
__device__ float g_bih1p[G3_];
__device__ float g_bhh1p[G3_];

// ===================== helpers =====================
__device__ __forceinline__ ull pack2(float lo, float hi) {
    ull r; asm("mov.b64 %0, {%1, %2};" : "=l"(r) : "f"(lo), "f"(hi)); return r;
}
__device__ __forceinline__ float2 unpack2(ull v) {
    float2 r; asm("mov.b64 {%0, %1}, %2;" : "=f"(r.x), "=f"(r.y) : "l"(v)); return r;
}
__device__ __forceinline__ void ffma2(ull& d, ull a, ull b) {
    asm("fma.rn.f32x2 %0, %1, %2, %3;" : "=l"(d) : "l"(a), "l"(b), "l"(d));
}
__device__ __forceinline__ float sigf(float x) { return 1.f / (1.f + __expf(-x)); }

// ===================== FFMA2 GEMM, pre-paired B =====================
// C[M x Nd] = A[M x K] @ W[Nd x K]^T (+bias).
// Row-pair packing (acc half = adjacent M rows); thread cols n = n0 + tx + 16*j.
// B stored in smem as duplicated (b,b) ull pairs -> mainloop has zero pack2.
#define BM 128
#define BN 96
#define BK 16

// dynamic smem layout (floats):
//   As: [16][132]            -> 2112 floats (8448 B)
//   Bs2: [16][97] ull        -> 1552 ull = 3104 floats (12416 B), 8B aligned
//   epilogue overlay [128][100] -> 12800 floats (reuses whole buffer)
#define AS_STRIDE 132
#define BS2_STRIDE 97
#define SMEMF 12800
#define SMEMSZ (SMEMF * 4)

__device__ __forceinline__ void load_tileA(const float* __restrict__ A, int M, int K,
                                           int m0, int k0, int am, int ak, float4* Apre)
{
    #pragma unroll
    for (int r = 0; r < 2; r++) {
        int gm = m0 + am + r * 64;
        int gk = k0 + ak;
        float4 v = make_float4(0.f, 0.f, 0.f, 0.f);
        if (gk + 3 < K) {
            v = *(const float4*)(A + (size_t)gm * K + gk);
        } else {
            if (gk + 0 < K) v.x = A[(size_t)gm * K + gk + 0];
            if (gk + 1 < K) v.y = A[(size_t)gm * K + gk + 1];
            if (gk + 2 < K) v.z = A[(size_t)gm * K + gk + 2];
            if (gk + 3 < K) v.w = A[(size_t)gm * K + gk + 3];
        }
        Apre[r] = v;
    }
}
__device__ __forceinline__ void load_tileB(const float* __restrict__ Bm, int Nd, int K,
                                           int n0, int k0, int tid, float2* Bpre)
{
    #pragma unroll
    for (int j = 0; j < 3; j++) {
        int i2 = tid + j * 256;
        int bn = i2 >> 3;
        int bk = (i2 & 7) << 1;
        int gn = n0 + bn, gk = k0 + bk;
        float2 v = make_float2(0.f, 0.f);
        if (gn < Nd && gk < K) v = *(const float2*)(Bm + (size_t)gn * K + gk);
        Bpre[j] = v;
    }
}

// mode 0: C[gm*ldC+gn] = sum + bias ; mode 1: fused GRU gates -> hout/seq
__global__ __launch_bounds__(256)
void gemm_pp(const float* __restrict__ A, const float* __restrict__ W,
             const float* __restrict__ bias,
             float* __restrict__ C, int ldC,
             const float* __restrict__ xp, const float* __restrict__ hin,
             float* __restrict__ hout, float* __restrict__ seqp,
             int Nd, int K, int t, int mode)
{
    extern __shared__ __align__(16) float sm[];
    float* As  = sm;                      // [16][132]
    ull*   Bs2 = (ull*)(sm + 2112);       // [16][97]

    const int tid = threadIdx.x;
    const int tx = tid & 15, ty = tid >> 4;
    const int m0 = blockIdx.y * BM, n0 = blockIdx.x * BN;
    const int am = tid >> 2;              // 0..63
    const int ak = (tid & 3) << 2;        // 0,4,8,12

    ull acc[4][6];
    #pragma unroll
    for (int i = 0; i < 4; i++)
        #pragma unroll
        for (int j = 0; j < 6; j++) acc[i][j] = 0ull;

    float4 Apre[2]; float2 Bpre[3];
    const int ntiles = (K + BK - 1) / BK;
    load_tileA(A, 0, K, m0, 0, am, ak, Apre);
    load_tileB(W, Nd, K, n0, 0, tid, Bpre);

    for (int kt = 0; kt < ntiles; kt++) {
        // stage A (transpose to [k][m])
        #pragma unroll
        for (int r = 0; r < 2; r++) {
            As[(ak + 0) * AS_STRIDE + am + r * 64] = Apre[r].x;
            As[(ak + 1) * AS_STRIDE + am + r * 64] = Apre[r].y;
            As[(ak + 2) * AS_STRIDE + am + r * 64] = Apre[r].z;
            As[(ak + 3) * AS_STRIDE + am + r * 64] = Apre[r].w;
        }
        // stage B pre-paired: Bs2[k][n] = (b, b)
        #pragma unroll
        for (int j = 0; j < 3; j++) {
            int i2 = tid + j * 256;
            int bn = i2 >> 3, bk = (i2 & 7) << 1;
            Bs2[(bk + 0) * BS2_STRIDE + bn] = pack2(Bpre[j].x, Bpre[j].x);
            Bs2[(bk + 1) * BS2_STRIDE + bn] = pack2(Bpre[j].y, Bpre[j].y);
        }
        __syncthreads();

        if (kt + 1 < ntiles) {
            load_tileA(A, 0, K, m0, (kt + 1) * BK, am, ak, Apre);
            load_tileB(W, Nd, K, n0, (kt + 1) * BK, tid, Bpre);
        }

        #pragma unroll
        for (int k = 0; k < BK; k++) {
            ull av[4];
            #pragma unroll
            for (int i = 0; i < 4; i++)
                av[i] = *(const ull*)&As[k * AS_STRIDE + ty * 8 + 2 * i];
            ull bv[6];
            #pragma unroll
            for (int j = 0; j < 6; j++)
                bv[j] = Bs2[k * BS2_STRIDE + tx + 16 * j];
            #pragma unroll
            for (int i = 0; i < 4; i++)
                #pragma unroll
                for (int j = 0; j < 6; j++) ffma2(acc[i][j], av[i], bv[j]);
        }
        __syncthreads();
    }

    if (mode == 0) {
        #pragma unroll
        for (int i = 0; i < 4; i++) {
            int gm0 = m0 + ty * 8 + 2 * i;
            #pragma unroll
            for (int j = 0; j < 6; j++) {
                int gn = n0 + tx + 16 * j;
                if (gn < Nd) {
                    float2 v = unpack2(acc[i][j]);
                    float bb = bias[gn];
                    C[(size_t)gm0 * ldC + gn]       = v.x + bb;
                    C[(size_t)(gm0 + 1) * ldC + gn] = v.y + bb;
                }
            }
        }
    } else {
        // overlay epilogue [128][100]
        #pragma unroll
        for (int i = 0; i < 4; i++) {
            int row = ty * 8 + 2 * i;
            #pragma unroll
            for (int j = 0; j < 6; j++) {
                int col = tx + 16 * j;
                float2 v = unpack2(acc[i][j]);
                sm[row * 100 + col]       = v.x;
                sm[(row + 1) * 100 + col] = v.y;
            }
        }
        __syncthreads();
        #pragma unroll
        for (int it = 0; it < 16; it++) {
            int unit = tid + it * 256;
            int u = unit & 31;           // triple 0..31
            int row = unit >> 5;         // 0..127
            int b = m0 + row;
            int c0 = 3 * u;
            float gr = sm[row * 100 + c0]     + bias[n0 + c0];
            float gz = sm[row * 100 + c0 + 1] + bias[n0 + c0 + 1];
            float gn = sm[row * 100 + c0 + 2] + bias[n0 + c0 + 2];
            const float* xr = xp + ((size_t)b * T_ + t) * G3_ + n0 + c0;
            float r  = sigf(xr[0] + gr);
            float z  = sigf(xr[1] + gz);
            float nn = tanhf(xr[2] + r * gn);
            int hu = n0 / 3 + u;
            float hp = hin[(size_t)b * H_ + hu];
            float hv = (1.f - z) * nn + z * hp;
            hout[(size_t)b * H_ + hu] = hv;
            if (seqp) seqp[((size_t)b * T_ + t) * H_ + hu] = hv;
        }
    }
}

// ===================== misc kernels =====================
__global__ void permute_w(const float* __restrict__ w, float* __restrict__ wp, int K)
{
    int c = blockIdx.y;
    int k = blockIdx.x * 256 + threadIdx.x;
    if (k >= K) return;
    int g = c % 3, h = c / 3;
    wp[(size_t)c * K + k] = w[(size_t)(g * H_ + h) * K + k];
}
__global__ void permute_b(const float* __restrict__ b, float* __restrict__ bp)
{
    int c = blockIdx.x * 256 + threadIdx.x;
    if (c < G3_) bp[c] = b[(c % 3) * H_ + c / 3];
}
__global__ void zero_kernel(float* __restrict__ p, int n)
{
    int i = blockIdx.x * blockDim.x + threadIdx.x;
    if (i < n) p[i] = 0.f;
}

__global__ __launch_bounds__(256)
void ln_silu(const float* __restrict__ z,
             const float* __restrict__ lng,
             const float* __restrict__ lnb,
             float* __restrict__ out)
{
    __shared__ float red[256];
    int b = blockIdx.x, tid = threadIdx.x;
    const float* row = z + (size_t)b * H_;
    float s = 0.f, s2 = 0.f;
    for (int i = tid; i < H_; i += 256) { float v = row[i]; s += v; s2 += v * v; }
    red[tid] = s; __syncthreads();
    for (int o = 128; o > 0; o >>= 1) { if (tid < o) red[tid] += red[tid + o]; __syncthreads(); }
    float mu = red[0] / H_;
    __syncthreads();
    red[tid] = s2; __syncthreads();
    for (int o = 128; o > 0; o >>= 1) { if (tid < o) red[tid] += red[tid + o]; __syncthreads(); }
    float var = red[0] / H_ - mu * mu;
    float inv = rsqrtf(var + 1e-5f);
    for (int i = tid; i < H_; i += 256) {
        float y = (row[i] - mu) * inv * lng[i] + lnb[i];
        out[(size_t)b * H_ + i] = y / (1.f + expf(-y));
    }
}

__global__ __launch_bounds__(512)
void softmax_rebalance(const float* __restrict__ scores,
                       float* __restrict__ out)
{
    __shared__ float red[512];
    int b = blockIdx.x, tid = threadIdx.x;
    float s = (tid < N_) ? scores[(size_t)b * N_ + tid] : -INFINITY;
    if (s < 0.f) s = -INFINITY;
    red[tid] = s; __syncthreads();
    for (int o = 256; o > 0; o >>= 1) { if (tid < o) red[tid] = fmaxf(red[tid], red[tid + o]); __syncthreads(); }
    float m = red[0]; __syncthreads();
    float e = (tid < N_) ? expf(s - m) : 0.f;
    red[tid] = e; __syncthreads();
    for (int o = 256; o > 0; o >>= 1) { if (tid < o) red[tid] += red[tid + o]; __syncthreads(); }
    float S = red[0]; __syncthreads();
    float w = e / S;
    w = fminf(fmaxf(w, 0.0f), 0.1f);
    for (int it = 0; it < 20; it++) {
        red[tid] = (tid < N_) ? w : 0.f; __syncthreads();
        for (int o = 256; o > 0; o >>= 1) { if (tid < o) red[tid] += red[tid + o]; __syncthreads(); }
        float tot = red[0]; __syncthreads();
        float excess = tot - 1.0f;
        bool  active = excess > 1e-6f;
        float sur = fmaxf(w - 0.1f, 0.f);
        red[tid] = (tid < N_) ? sur : 0.f; __syncthreads();
        for (int o = 256; o > 0; o >>= 1) { if (tid < o) red[tid] += red[tid + o]; __syncthreads(); }
        float totsur = red[0]; __syncthreads();
        float upd = (totsur > 0.f)
                  ? w - sur / fmaxf(totsur, 1e-12f) * excess
                  : w - excess / (float)N_;
        upd = fminf(fmaxf(upd, 0.0f), 0.1f);
        if (active) w = upd;
    }
    if (tid < N_) out[(size_t)b * N_ + tid] = w;
}

// ===================== orchestration =====================
extern "C" void kernel_launch(void* const* d_in, const int* in_sizes, int n_in,
                              void* d_out, int out_size)
{
    const float* x     = (const float*)d_in[0];
    const float* w_ih0 = (const float*)d_in[1];
    const float* w_hh0 = (const float*)d_in[2];
    const float* b_ih0 = (const float*)d_in[3];
    const float* b_hh0 = (const float*)d_in[4];
    const float* w_ih1 = (const float*)d_in[5];
    const float* w_hh1 = (const float*)d_in[6];
    const float* b_ih1 = (const float*)d_in[7];
    const float* b_hh1 = (const float*)d_in[8];
    const float* w1    = (const float*)d_in[9];
    const float* b1    = (const float*)d_in[10];
    const float* ln_g  = (const float*)d_in[11];
    const float* ln_b  = (const float*)d_in[12];
    const float* w2    = (const float*)d_in[13];
    const float* b2    = (const float*)d_in[14];
    float* out = (float*)d_out;

    void* p;
    float *xproj, *seq, *h0, *h1, *z, *za, *scores;
    float *wih0p, *whh0p, *wih1p, *whh1p, *bih0p, *bhh0p, *bih1p, *bhh1p;
    cudaGetSymbolAddress(&p, g_xproj);  xproj  = (float*)p;
    cudaGetSymbolAddress(&p, g_seq);    seq    = (float*)p;
    cudaGetSymbolAddress(&p, g_h0);     h0     = (float*)p;
    cudaGetSymbolAddress(&p, g_h1);     h1     = (float*)p;
    cudaGetSymbolAddress(&p, g_z);      z      = (float*)p;
    cudaGetSymbolAddress(&p, g_za);     za     = (float*)p;
    cudaGetSymbolAddress(&p, g_scores); scores = (float*)p;
    cudaGetSymbolAddress(&p, g_wih0p);  wih0p  = (float*)p;
    cudaGetSymbolAddress(&p, g_whh0p);  whh0p  = (float*)p;
    cudaGetSymbolAddress(&p, g_wih1p);  wih1p  = (float*)p;
    cudaGetSymbolAddress(&p, g_whh1p);  whh1p  = (float*)p;
    cudaGetSymbolAddress(&p, g_bih0p);  bih0p  = (float*)p;
    cudaGetSymbolAddress(&p, g_bhh0p);  bhh0p  = (float*)p;
    cudaGetSymbolAddress(&p, g_bih1p);  bih1p  = (float*)p;
    cudaGetSymbolAddress(&p, g_bhh1p);  bhh1p  = (float*)p;

    cudaFuncSetAttribute(gemm_pp, cudaFuncAttributeMaxDynamicSharedMemorySize, SMEMSZ);

    // permute weights/biases into gate-interleaved layout (h*3+g)
    permute_w<<<dim3((N_ + 255) / 256, G3_), 256>>>(w_ih0, wih0p, N_);
    permute_w<<<dim3((H_ + 255) / 256, G3_), 256>>>(w_hh0, whh0p, H_);
    permute_w<<<dim3((H_ + 255) / 256, G3_), 256>>>(w_ih1, wih1p, H_);
    permute_w<<<dim3((H_ + 255) / 256, G3_), 256>>>(w_hh1, whh1p, H_);
    permute_b<<<(G3_ + 255) / 256, 256>>>(b_ih0, bih0p);
    permute_b<<<(G3_ + 255) / 256, 256>>>(b_hh0, bhh0p);
    permute_b<<<(G3_ + 255) / 256, 256>>>(b_ih1, bih1p);
    permute_b<<<(G3_ + 255) / 256, 256>>>(b_hh1, bhh1p);

    // layer 0 input projection: xproj = x @ wih0p^T + bih0p
    gemm_pp<<<dim3(G3_ / BN, BT_ / BM), 256, SMEMSZ>>>(
        x, wih0p, bih0p, xproj, G3_, nullptr, nullptr, nullptr, nullptr, G3_, N_, 0, 0);
    zero_kernel<<<(B_ * H_ + 255) / 256, 256>>>(h0, B_ * H_);

    // layer 0 recurrence (fused GEMM + gates)
    for (int t = 0; t < T_; t++) {
        float* hin  = (t & 1) ? h1 : h0;
        float* hout = (t & 1) ? h0 : h1;
        gemm_pp<<<dim3(G3_ / BN, B_ / BM), 256, SMEMSZ>>>(
            hin, whh0p, bhh0p, nullptr, 0, xproj, hin, hout, seq, G3_, H_, t, 1);
    }

    // layer 1 input projection
    gemm_pp<<<dim3(G3_ / BN, BT_ / BM), 256, SMEMSZ>>>(
        seq, wih1p, bih1p, xproj, G3_, nullptr, nullptr, nullptr, nullptr, G3_, H_, 0, 0);
    zero_kernel<<<(B_ * H_ + 255) / 256, 256>>>(h0, B_ * H_);

    // layer 1 recurrence
    for (int t = 0; t < T_; t++) {
        float* hin  = (t & 1) ? h1 : h0;
        float* hout = (t & 1) ? h0 : h1;
        gemm_pp<<<dim3(G3_ / BN, B_ / BM), 256, SMEMSZ>>>(
            hin, whh1p, bhh1p, nullptr, 0, xproj, hin, hout, nullptr, G3_, H_, t, 1);
    }

    // head
    gemm_pp<<<dim3((H_ + BN - 1) / BN, B_ / BM), 256, SMEMSZ>>>(
        h0, w1, b1, z, H_, nullptr, nullptr, nullptr, nullptr, H_, H_, 0, 0);
    ln_silu<<<B_, 256>>>(z, ln_g, ln_b, za);
    gemm_pp<<<dim3((N_ + BN - 1) / BN, B_ / BM), 256, SMEMSZ>>>(
        za, w2, b2, scores, N_, nullptr, nullptr, nullptr, nullptr, N_, H_, 0, 0);
    softmax_rebalance<<<B_, 512>>>(scores, out);
}

// round 10
// speedup vs baseline: 1.2627x; 1.1523x over previous
#include <cuda_runtime.h>
#include <math.h>
#include <stdint.h>

#define B_   512
#define T_   128
#define N_   500
#define H_   1024
#define G3_  3072
#define BT_  65536

typedef unsigned long long ull;

// ===================== static device scratch =====================
__device__ float g_xproj[(size_t)BT_ * G3_];
__device__ float g_seq  [(size_t)BT_ * H_];
__device__ float g_h0   [B_ * H_];
__device__ float g_h1   [B_ * H_];
__device__ float g_z    [B_ * H_];
__device__ float g_za   [B_ * H_];
__device__ float g_scores[B_ * N_];
__device__ float g_wih0p[(size_t)G3_ * N_];
__device__ float g_whh0p[(size_t)G3_ * H_];
__device__ float g_wih1p[(size_t)G3_ * H_];
__device__ float g_whh1p[(size_t)G3_ * H_];
__device__ float g_bih0p[G3_];
__device__ float g_bhh0p[G3_];
__device__ float g_bih1p[G3_];
__device__ float g_bhh1p[G3_];

// ===================== helpers =====================
__device__ __forceinline__ ull pack2(float lo, float hi) {
    ull r; asm("mov.b64 %0, {%1, %2};" : "=l"(r) : "f"(lo), "f"(hi)); return r;
}
__device__ __forceinline__ float2 unpack2(ull v) {
    float2 r; asm("mov.b64 {%0, %1}, %2;" : "=f"(r.x), "=f"(r.y) : "l"(v)); return r;
}
__device__ __forceinline__ void ffma2(ull& d, ull a, ull b) {
    asm("fma.rn.f32x2 %0, %1, %2, %3;" : "=l"(d) : "l"(a), "l"(b), "l"(d));
}
__device__ __forceinline__ float sigf(float x) { return 1.f / (1.f + __expf(-x)); }

// ===================== FFMA2 GEMM (projections + head) — R2 verbatim ============
#define BM 128
#define BN 96
#define BK 16
#define NT 256

__device__ __forceinline__ void load_tileA(const float* __restrict__ A, int M, int K,
                                           int m0, int k0, int am, int ak, float4* Apre)
{
    #pragma unroll
    for (int r = 0; r < 2; r++) {
        int gm = m0 + am + r * 64;
        int gk = k0 + ak;
        float4 v = make_float4(0.f, 0.f, 0.f, 0.f);
        if (gm < M) {
            if (gk + 3 < K) v = *(const float4*)(A + (size_t)gm * K + gk);
            else {
                if (gk + 0 < K) v.x = A[(size_t)gm * K + gk + 0];
                if (gk + 1 < K) v.y = A[(size_t)gm * K + gk + 1];
                if (gk + 2 < K) v.z = A[(size_t)gm * K + gk + 2];
                if (gk + 3 < K) v.w = A[(size_t)gm * K + gk + 3];
            }
        }
        Apre[r] = v;
    }
}
__device__ __forceinline__ void load_tileB(const float* __restrict__ Bm, int Nd, int K,
                                           int n0, int k0, int tid, float2* Bpre)
{
    #pragma unroll
    for (int j = 0; j < 3; j++) {
        int i2 = tid + j * 256;
        int bn = i2 >> 3;
        int bk = (i2 & 7) << 1;
        int gn = n0 + bn, gk = k0 + bk;
        float2 v = make_float2(0.f, 0.f);
        if (gn < Nd && gk < K) v = *(const float2*)(Bm + (size_t)gn * K + gk);
        Bpre[j] = v;
    }
}

__global__ __launch_bounds__(NT)
void gemm_f2(const float* __restrict__ A, const float* __restrict__ Bm,
             const float* __restrict__ bias, float* __restrict__ C,
             int M, int Nd, int K)
{
    __shared__ float As[BK][BM + 4];
    __shared__ float Bs[BK][BN + 2];
    const int tid = threadIdx.x;
    const int tx = tid & 15, ty = tid >> 4;
    const int m0 = blockIdx.y * BM, n0 = blockIdx.x * BN;
    const int am = tid >> 2;
    const int ak = (tid & 3) << 2;
    ull acc[4][6];
    #pragma unroll
    for (int i = 0; i < 4; i++)
        #pragma unroll
        for (int j = 0; j < 6; j++) acc[i][j] = 0ull;
    float4 Apre[2]; float2 Bpre[3];
    const int ntiles = (K + BK - 1) / BK;
    load_tileA(A, M, K, m0, 0, am, ak, Apre);
    load_tileB(Bm, Nd, K, n0, 0, tid, Bpre);
    for (int kt = 0; kt < ntiles; kt++) {
        #pragma unroll
        for (int r = 0; r < 2; r++) {
            As[ak + 0][am + r * 64] = Apre[r].x;
            As[ak + 1][am + r * 64] = Apre[r].y;
            As[ak + 2][am + r * 64] = Apre[r].z;
            As[ak + 3][am + r * 64] = Apre[r].w;
        }
        #pragma unroll
        for (int j = 0; j < 3; j++) {
            int i2 = tid + j * 256;
            int bn = i2 >> 3, bk = (i2 & 7) << 1;
            Bs[bk][bn]     = Bpre[j].x;
            Bs[bk + 1][bn] = Bpre[j].y;
        }
        __syncthreads();
        if (kt + 1 < ntiles) {
            load_tileA(A, M, K, m0, (kt + 1) * BK, am, ak, Apre);
            load_tileB(Bm, Nd, K, n0, (kt + 1) * BK, tid, Bpre);
        }
        #pragma unroll
        for (int k = 0; k < BK; k++) {
            ull av[4];
            #pragma unroll
            for (int i = 0; i < 4; i++) av[i] = *(const ull*)&As[k][ty * 8 + 2 * i];
            ull bv[6];
            #pragma unroll
            for (int j = 0; j < 6; j++) { float b = Bs[k][tx * 6 + j]; bv[j] = pack2(b, b); }
            #pragma unroll
            for (int i = 0; i < 4; i++)
                #pragma unroll
                for (int j = 0; j < 6; j++) ffma2(acc[i][j], av[i], bv[j]);
        }
        __syncthreads();
    }
    #pragma unroll
    for (int i = 0; i < 4; i++) {
        int gm0 = m0 + ty * 8 + 2 * i;
        #pragma unroll
        for (int j = 0; j < 6; j++) {
            int gn = n0 + tx * 6 + j;
            if (gn >= Nd) continue;
            float2 v = unpack2(acc[i][j]);
            float bb = bias ? bias[gn] : 0.f;
            if (gm0 < M)     C[(size_t)gm0 * Nd + gn]       = v.x + bb;
            if (gm0 + 1 < M) C[(size_t)(gm0 + 1) * Nd + gn] = v.y + bb;
        }
    }
}

// ===================== recurrence GEMM+gates, tile 128x48 (grid 256) =============
// Each thread owns ONE gate triple (cols n0 + tx*3 .. +2) x 8 rows (4 pairs).
// K-order identical to gemm_f2 -> numerics unchanged.
#define RBN 48

__global__ __launch_bounds__(256)
void gru_step48(const float* __restrict__ hin, const float* __restrict__ W,
                const float* __restrict__ bias, const float* __restrict__ xp,
                float* __restrict__ hout, float* __restrict__ seqp, int t)
{
    __shared__ float As[BK][BM + 4];
    __shared__ float Bs[BK][RBN + 4];
    const int tid = threadIdx.x;
    const int tx = tid & 15, ty = tid >> 4;
    const int m0 = blockIdx.y * BM, n0 = blockIdx.x * RBN;
    const int am = tid >> 2;
    const int ak = (tid & 3) << 2;

    ull acc[4][3];
    #pragma unroll
    for (int i = 0; i < 4; i++)
        #pragma unroll
        for (int j = 0; j < 3; j++) acc[i][j] = 0ull;

    float4 Apre[2]; float2 Bpre[2];
    const int ntiles = H_ / BK;   // 64, K = H_ aligned

    // prologue loads (no guards: M=512, K=1024, rows<3072 all aligned)
    #pragma unroll
    for (int r = 0; r < 2; r++)
        Apre[r] = *(const float4*)(hin + (size_t)(m0 + am + r * 64) * H_ + ak);
    if (tid < 192) {
        #pragma unroll
        for (int j = 0; j < 2; j++) {
            int i2 = tid + j * 192;
            int bn = i2 >> 3, bk = (i2 & 7) << 1;
            Bpre[j] = *(const float2*)(W + (size_t)(n0 + bn) * H_ + bk);
        }
    }

    for (int kt = 0; kt < ntiles; kt++) {
        #pragma unroll
        for (int r = 0; r < 2; r++) {
            As[ak + 0][am + r * 64] = Apre[r].x;
            As[ak + 1][am + r * 64] = Apre[r].y;
            As[ak + 2][am + r * 64] = Apre[r].z;
            As[ak + 3][am + r * 64] = Apre[r].w;
        }
        if (tid < 192) {
            #pragma unroll
            for (int j = 0; j < 2; j++) {
                int i2 = tid + j * 192;
                int bn = i2 >> 3, bk = (i2 & 7) << 1;
                Bs[bk][bn]     = Bpre[j].x;
                Bs[bk + 1][bn] = Bpre[j].y;
            }
        }
        __syncthreads();

        if (kt + 1 < ntiles) {
            int k0 = (kt + 1) * BK;
            #pragma unroll
            for (int r = 0; r < 2; r++)
                Apre[r] = *(const float4*)(hin + (size_t)(m0 + am + r * 64) * H_ + k0 + ak);
            if (tid < 192) {
                #pragma unroll
                for (int j = 0; j < 2; j++) {
                    int i2 = tid + j * 192;
                    int bn = i2 >> 3, bk = (i2 & 7) << 1;
                    Bpre[j] = *(const float2*)(W + (size_t)(n0 + bn) * H_ + k0 + bk);
                }
            }
        }

        #pragma unroll
        for (int k = 0; k < BK; k++) {
            ull av[4];
            #pragma unroll
            for (int i = 0; i < 4; i++) av[i] = *(const ull*)&As[k][ty * 8 + 2 * i];
            ull bv[3];
            #pragma unroll
            for (int j = 0; j < 3; j++) { float b = Bs[k][tx * 3 + j]; bv[j] = pack2(b, b); }
            #pragma unroll
            for (int i = 0; i < 4; i++)
                #pragma unroll
                for (int j = 0; j < 3; j++) ffma2(acc[i][j], av[i], bv[j]);
        }
        __syncthreads();
    }

    // direct gate epilogue: this thread's triple
    const int c0 = n0 + tx * 3;
    const int hu = n0 / 3 + tx;
    const float b0 = bias[c0], b1 = bias[c0 + 1], b2 = bias[c0 + 2];

    #pragma unroll
    for (int i = 0; i < 4; i++) {
        int bm0 = m0 + ty * 8 + 2 * i;
        float2 v0 = unpack2(acc[i][0]);
        float2 v1 = unpack2(acc[i][1]);
        float2 v2 = unpack2(acc[i][2]);
        #pragma unroll
        for (int e = 0; e < 2; e++) {
            int b = bm0 + e;
            float g0 = (e ? v0.y : v0.x) + b0;
            float g1 = (e ? v1.y : v1.x) + b1;
            float g2 = (e ? v2.y : v2.x) + b2;
            const float* xr = xp + ((size_t)b * T_ + t) * G3_ + c0;
            float r  = sigf(xr[0] + g0);
            float z  = sigf(xr[1] + g1);
            float nn = tanhf(xr[2] + r * g2);
            float hp = hin[(size_t)b * H_ + hu];
            float hv = (1.f - z) * nn + z * hp;
            hout[(size_t)b * H_ + hu] = hv;
            if (seqp) seqp[((size_t)b * T_ + t) * H_ + hu] = hv;
        }
    }
}

// ===================== misc kernels =====================
__global__ void permute_w(const float* __restrict__ w, float* __restrict__ wp, int K)
{
    int c = blockIdx.y;
    int k = blockIdx.x * 256 + threadIdx.x;
    if (k >= K) return;
    int g = c % 3, h = c / 3;
    wp[(size_t)c * K + k] = w[(size_t)(g * H_ + h) * K + k];
}
__global__ void permute_b(const float* __restrict__ b, float* __restrict__ bp)
{
    int c = blockIdx.x * 256 + threadIdx.x;
    if (c < G3_) bp[c] = b[(c % 3) * H_ + c / 3];
}
__global__ void zero_kernel(float* __restrict__ p, int n)
{
    int i = blockIdx.x * blockDim.x + threadIdx.x;
    if (i < n) p[i] = 0.f;
}

__global__ __launch_bounds__(256)
void ln_silu(const float* __restrict__ z,
             const float* __restrict__ lng,
             const float* __restrict__ lnb,
             float* __restrict__ out)
{
    __shared__ float red[256];
    int b = blockIdx.x, tid = threadIdx.x;
    const float* row = z + (size_t)b * H_;
    float s = 0.f, s2 = 0.f;
    for (int i = tid; i < H_; i += 256) { float v = row[i]; s += v; s2 += v * v; }
    red[tid] = s; __syncthreads();
    for (int o = 128; o > 0; o >>= 1) { if (tid < o) red[tid] += red[tid + o]; __syncthreads(); }
    float mu = red[0] / H_;
    __syncthreads();
    red[tid] = s2; __syncthreads();
    for (int o = 128; o > 0; o >>= 1) { if (tid < o) red[tid] += red[tid + o]; __syncthreads(); }
    float var = red[0] / H_ - mu * mu;
    float inv = rsqrtf(var + 1e-5f);
    for (int i = tid; i < H_; i += 256) {
        float y = (row[i] - mu) * inv * lng[i] + lnb[i];
        out[(size_t)b * H_ + i] = y / (1.f + expf(-y));
    }
}

__global__ __launch_bounds__(512)
void softmax_rebalance(const float* __restrict__ scores,
                       float* __restrict__ out)
{
    __shared__ float red[512];
    int b = blockIdx.x, tid = threadIdx.x;
    float s = (tid < N_) ? scores[(size_t)b * N_ + tid] : -INFINITY;
    if (s < 0.f) s = -INFINITY;
    red[tid] = s; __syncthreads();
    for (int o = 256; o > 0; o >>= 1) { if (tid < o) red[tid] = fmaxf(red[tid], red[tid + o]); __syncthreads(); }
    float m = red[0]; __syncthreads();
    float e = (tid < N_) ? expf(s - m) : 0.f;
    red[tid] = e; __syncthreads();
    for (int o = 256; o > 0; o >>= 1) { if (tid < o) red[tid] += red[tid + o]; __syncthreads(); }
    float S = red[0]; __syncthreads();
    float w = e / S;
    w = fminf(fmaxf(w, 0.0f), 0.1f);
    for (int it = 0; it < 20; it++) {
        red[tid] = (tid < N_) ? w : 0.f; __syncthreads();
        for (int o = 256; o > 0; o >>= 1) { if (tid < o) red[tid] += red[tid + o]; __syncthreads(); }
        float tot = red[0]; __syncthreads();
        float excess = tot - 1.0f;
        bool  active = excess > 1e-6f;
        float sur = fmaxf(w - 0.1f, 0.f);
        red[tid] = (tid < N_) ? sur : 0.f; __syncthreads();
        for (int o = 256; o > 0; o >>= 1) { if (tid < o) red[tid] += red[tid + o]; __syncthreads(); }
        float totsur = red[0]; __syncthreads();
        float upd = (totsur > 0.f)
                  ? w - sur / fmaxf(totsur, 1e-12f) * excess
                  : w - excess / (float)N_;
        upd = fminf(fmaxf(upd, 0.0f), 0.1f);
        if (active) w = upd;
    }
    if (tid < N_) out[(size_t)b * N_ + tid] = w;
}

// ===================== orchestration =====================
extern "C" void kernel_launch(void* const* d_in, const int* in_sizes, int n_in,
                              void* d_out, int out_size)
{
    const float* x     = (const float*)d_in[0];
    const float* w_ih0 = (const float*)d_in[1];
    const float* w_hh0 = (const float*)d_in[2];
    const float* b_ih0 = (const float*)d_in[3];
    const float* b_hh0 = (const float*)d_in[4];
    const float* w_ih1 = (const float*)d_in[5];
    const float* w_hh1 = (const float*)d_in[6];
    const float* b_ih1 = (const float*)d_in[7];
    const float* b_hh1 = (const float*)d_in[8];
    const float* w1    = (const float*)d_in[9];
    const float* b1    = (const float*)d_in[10];
    const float* ln_g  = (const float*)d_in[11];
    const float* ln_b  = (const float*)d_in[12];
    const float* w2    = (const float*)d_in[13];
    const float* b2    = (const float*)d_in[14];
    float* out = (float*)d_out;

    void* p;
    float *xproj, *seq, *h0, *h1, *z, *za, *scores;
    float *wih0p, *whh0p, *wih1p, *whh1p, *bih0p, *bhh0p, *bih1p, *bhh1p;
    cudaGetSymbolAddress(&p, g_xproj);  xproj  = (float*)p;
    cudaGetSymbolAddress(&p, g_seq);    seq    = (float*)p;
    cudaGetSymbolAddress(&p, g_h0);     h0     = (float*)p;
    cudaGetSymbolAddress(&p, g_h1);     h1     = (float*)p;
    cudaGetSymbolAddress(&p, g_z);      z      = (float*)p;
    cudaGetSymbolAddress(&p, g_za);     za     = (float*)p;
    cudaGetSymbolAddress(&p, g_scores); scores = (float*)p;
    cudaGetSymbolAddress(&p, g_wih0p);  wih0p  = (float*)p;
    cudaGetSymbolAddress(&p, g_whh0p);  whh0p  = (float*)p;
    cudaGetSymbolAddress(&p, g_wih1p);  wih1p  = (float*)p;
    cudaGetSymbolAddress(&p, g_whh1p);  whh1p  = (float*)p;
    cudaGetSymbolAddress(&p, g_bih0p);  bih0p  = (float*)p;
    cudaGetSymbolAddress(&p, g_bhh0p);  bhh0p  = (float*)p;
    cudaGetSymbolAddress(&p, g_bih1p);  bih1p  = (float*)p;
    cudaGetSymbolAddress(&p, g_bhh1p);  bhh1p  = (float*)p;

    // permute weights/biases into gate-interleaved layout (h*3+g)
    permute_w<<<dim3((N_ + 255) / 256, G3_), 256>>>(w_ih0, wih0p, N_);
    permute_w<<<dim3((H_ + 255) / 256, G3_), 256>>>(w_hh0, whh0p, H_);
    permute_w<<<dim3((H_ + 255) / 256, G3_), 256>>>(w_ih1, wih1p, H_);
    permute_w<<<dim3((H_ + 255) / 256, G3_), 256>>>(w_hh1, whh1p, H_);
    permute_b<<<(G3_ + 255) / 256, 256>>>(b_ih0, bih0p);
    permute_b<<<(G3_ + 255) / 256, 256>>>(b_hh0, bhh0p);
    permute_b<<<(G3_ + 255) / 256, 256>>>(b_ih1, bih1p);
    permute_b<<<(G3_ + 255) / 256, 256>>>(b_hh1, bhh1p);

    // layer 0 input projection: xproj = x @ wih0p^T + bih0p
    gemm_f2<<<dim3(G3_ / BN, BT_ / BM), NT>>>(x, wih0p, bih0p, xproj, BT_, G3_, N_);
    zero_kernel<<<(B_ * H_ + 255) / 256, 256>>>(h0, B_ * H_);

    // layer 0 recurrence (fused GEMM + gates), grid 64x4 = 256 blocks
    for (int t = 0; t < T_; t++) {
        float* hin  = (t & 1) ? h1 : h0;
        float* hout = (t & 1) ? h0 : h1;
        gru_step48<<<dim3(G3_ / RBN, B_ / BM), 256>>>(hin, whh0p, bhh0p, xproj, hout, seq, t);
    }

    // layer 1 input projection
    gemm_f2<<<dim3(G3_ / BN, BT_ / BM), NT>>>(seq, wih1p, bih1p, xproj, BT_, G3_, H_);
    zero_kernel<<<(B_ * H_ + 255) / 256, 256>>>(h0, B_ * H_);

    // layer 1 recurrence
    for (int t = 0; t < T_; t++) {
        float* hin  = (t & 1) ? h1 : h0;
        float* hout = (t & 1) ? h0 : h1;
        gru_step48<<<dim3(G3_ / RBN, B_ / BM), 256>>>(hin, whh1p, bhh1p, xproj, hout, nullptr, t);
    }

    // head
    gemm_f2<<<dim3((H_ + BN - 1) / BN, B_ / BM), NT>>>(h0, w1, b1, z, B_, H_, H_);
    ln_silu<<<B_, 256>>>(z, ln_g, ln_b, za);
    gemm_f2<<<dim3((N_ + BN - 1) / BN, B_ / BM), NT>>>(za, w2, b2, scores, B_, N_, H_);
    softmax_rebalance<<<B_, 512>>>(scores, out);
}

// round 11
// speedup vs baseline: 1.3074x; 1.0354x over previous
#include <cuda_runtime.h>
#include <math.h>
#include <stdint.h>

#define B_   512
#define T_   128
#define N_   500
#define H_   1024
#define G3_  3072
#define BT_  65536

typedef unsigned long long ull;

// ===================== static device scratch =====================
__device__ float g_xproj[(size_t)BT_ * G3_];
__device__ float g_seq  [(size_t)BT_ * H_];
__device__ float g_h0   [B_ * H_];
__device__ float g_h1   [B_ * H_];
__device__ float g_z    [B_ * H_];
__device__ float g_za   [B_ * H_];
__device__ float g_scores[B_ * N_];
__device__ float g_wih0p[(size_t)G3_ * N_];
__device__ float g_whh0p[(size_t)G3_ * H_];
__device__ float g_wih1p[(size_t)G3_ * H_];
__device__ float g_whh1p[(size_t)G3_ * H_];
__device__ float g_bih0p[G3_];
__device__ float g_bhh0p[G3_];
__device__ float g_bih1p[G3_];
__device__ float g_bhh1p[G3_];

// ===================== helpers =====================
__device__ __forceinline__ ull pack2(float lo, float hi) {
    ull r; asm("mov.b64 %0, {%1, %2};" : "=l"(r) : "f"(lo), "f"(hi)); return r;
}
__device__ __forceinline__ float2 unpack2(ull v) {
    float2 r; asm("mov.b64 {%0, %1}, %2;" : "=f"(r.x), "=f"(r.y) : "l"(v)); return r;
}
__device__ __forceinline__ void ffma2(ull& d, ull a, ull b) {
    asm("fma.rn.f32x2 %0, %1, %2, %3;" : "=l"(d) : "l"(a), "l"(b), "l"(d));
}
__device__ __forceinline__ float sigf(float x) { return 1.f / (1.f + __expf(-x)); }

// ===================== double-buffered FFMA2 GEMM =====================
// R2 tile/mapping/K-order exactly; 2 smem stages, ONE __syncthreads per K-tile.
// mode 0: C[M x Nd] = A @ W^T + bias   (row stride Nd)
// mode 1: fused GRU step; cols = n0 + tx*6 (two whole gate triples / thread)
#define BM 128
#define BN 96
#define BK 16
#define NT 256

struct Stage {
    float As[BK][BM + 4];
    float Bs[BK][BN + 2];
};

__device__ __forceinline__ void load_tileA(const float* __restrict__ A, int M, int K,
                                           int m0, int k0, int am, int ak, float4* Apre)
{
    #pragma unroll
    for (int r = 0; r < 2; r++) {
        int gm = m0 + am + r * 64;
        int gk = k0 + ak;
        float4 v = make_float4(0.f, 0.f, 0.f, 0.f);
        if (gm < M) {
            if (gk + 3 < K) v = *(const float4*)(A + (size_t)gm * K + gk);
            else {
                if (gk + 0 < K) v.x = A[(size_t)gm * K + gk + 0];
                if (gk + 1 < K) v.y = A[(size_t)gm * K + gk + 1];
                if (gk + 2 < K) v.z = A[(size_t)gm * K + gk + 2];
                if (gk + 3 < K) v.w = A[(size_t)gm * K + gk + 3];
            }
        }
        Apre[r] = v;
    }
}
__device__ __forceinline__ void load_tileB(const float* __restrict__ Bm, int Nd, int K,
                                           int n0, int k0, int tid, float2* Bpre)
{
    #pragma unroll
    for (int j = 0; j < 3; j++) {
        int i2 = tid + j * 256;
        int bn = i2 >> 3;
        int bk = (i2 & 7) << 1;
        int gn = n0 + bn, gk = k0 + bk;
        float2 v = make_float2(0.f, 0.f);
        if (gn < Nd && gk < K) v = *(const float2*)(Bm + (size_t)gn * K + gk);
        Bpre[j] = v;
    }
}
__device__ __forceinline__ void store_stage(Stage* st, int tid, int am, int ak,
                                            const float4* Apre, const float2* Bpre)
{
    #pragma unroll
    for (int r = 0; r < 2; r++) {
        st->As[ak + 0][am + r * 64] = Apre[r].x;
        st->As[ak + 1][am + r * 64] = Apre[r].y;
        st->As[ak + 2][am + r * 64] = Apre[r].z;
        st->As[ak + 3][am + r * 64] = Apre[r].w;
    }
    #pragma unroll
    for (int j = 0; j < 3; j++) {
        int i2 = tid + j * 256;
        int bn = i2 >> 3, bk = (i2 & 7) << 1;
        st->Bs[bk][bn]     = Bpre[j].x;
        st->Bs[bk + 1][bn] = Bpre[j].y;
    }
}

__global__ __launch_bounds__(NT)
void gemm_db(const float* __restrict__ A, const float* __restrict__ W,
             const float* __restrict__ bias,
             float* __restrict__ C,
             const float* __restrict__ xp, const float* __restrict__ hin,
             float* __restrict__ hout, float* __restrict__ seqp,
             int M, int Nd, int K, int t, int mode)
{
    __shared__ Stage stg[2];

    const int tid = threadIdx.x;
    const int tx = tid & 15, ty = tid >> 4;
    const int m0 = blockIdx.y * BM, n0 = blockIdx.x * BN;
    const int am = tid >> 2;
    const int ak = (tid & 3) << 2;

    ull acc[4][6];
    #pragma unroll
    for (int i = 0; i < 4; i++)
        #pragma unroll
        for (int j = 0; j < 6; j++) acc[i][j] = 0ull;

    float4 Apre[2]; float2 Bpre[3];
    const int ntiles = (K + BK - 1) / BK;
    load_tileA(A, M, K, m0, 0, am, ak, Apre);
    load_tileB(W, Nd, K, n0, 0, tid, Bpre);

    for (int kt = 0; kt < ntiles; kt++) {
        Stage* st = &stg[kt & 1];
        store_stage(st, tid, am, ak, Apre, Bpre);
        __syncthreads();                       // ONE barrier per K-tile

        if (kt + 1 < ntiles) {                 // prefetch next tile (LDG overlaps compute)
            load_tileA(A, M, K, m0, (kt + 1) * BK, am, ak, Apre);
            load_tileB(W, Nd, K, n0, (kt + 1) * BK, tid, Bpre);
        }

        #pragma unroll
        for (int k = 0; k < BK; k++) {
            ull av[4];
            #pragma unroll
            for (int i = 0; i < 4; i++) av[i] = *(const ull*)&st->As[k][ty * 8 + 2 * i];
            ull bv[6];
            #pragma unroll
            for (int j = 0; j < 6; j++) { float b = st->Bs[k][tx * 6 + j]; bv[j] = pack2(b, b); }
            #pragma unroll
            for (int i = 0; i < 4; i++)
                #pragma unroll
                for (int j = 0; j < 6; j++) ffma2(acc[i][j], av[i], bv[j]);
        }
    }

    if (mode == 0) {
        #pragma unroll
        for (int i = 0; i < 4; i++) {
            int gm0 = m0 + ty * 8 + 2 * i;
            #pragma unroll
            for (int j = 0; j < 6; j++) {
                int gn = n0 + tx * 6 + j;
                if (gn >= Nd) continue;
                float2 v = unpack2(acc[i][j]);
                float bb = bias ? bias[gn] : 0.f;
                if (gm0 < M)     C[(size_t)gm0 * Nd + gn]       = v.x + bb;
                if (gm0 + 1 < M) C[(size_t)(gm0 + 1) * Nd + gn] = v.y + bb;
            }
        }
    } else {
        // R2 direct gate epilogue: cols n0+tx*6 .. +5 = two whole triples
        const int col0 = n0 + tx * 6;
        const int hu0  = col0 / 3;
        #pragma unroll
        for (int i = 0; i < 4; i++) {
            int b0 = m0 + ty * 8 + 2 * i;
            float ga[6], gb[6];
            #pragma unroll
            for (int j = 0; j < 6; j++) {
                float2 v = unpack2(acc[i][j]);
                ga[j] = v.x + bias[col0 + j];
                gb[j] = v.y + bias[col0 + j];
            }
            #pragma unroll
            for (int e = 0; e < 2; e++) {
                int b = b0 + e;
                const float* gg = e ? gb : ga;
                const float* xr = xp + ((size_t)b * T_ + t) * G3_ + col0;
                #pragma unroll
                for (int u = 0; u < 2; u++) {
                    int c  = 3 * u;
                    int hu = hu0 + u;
                    float r  = sigf(xr[c + 0] + gg[c + 0]);
                    float z  = sigf(xr[c + 1] + gg[c + 1]);
                    float nn = tanhf(xr[c + 2] + r * gg[c + 2]);
                    float hp = hin[(size_t)b * H_ + hu];
                    float hv = (1.f - z) * nn + z * hp;
                    hout[(size_t)b * H_ + hu] = hv;
                    if (seqp) seqp[((size_t)b * T_ + t) * H_ + hu] = hv;
                }
            }
        }
    }
}

// ===================== misc kernels =====================
__global__ void permute_w(const float* __restrict__ w, float* __restrict__ wp, int K)
{
    int c = blockIdx.y;
    int k = blockIdx.x * 256 + threadIdx.x;
    if (k >= K) return;
    int g = c % 3, h = c / 3;
    wp[(size_t)c * K + k] = w[(size_t)(g * H_ + h) * K + k];
}
__global__ void permute_b(const float* __restrict__ b, float* __restrict__ bp)
{
    int c = blockIdx.x * 256 + threadIdx.x;
    if (c < G3_) bp[c] = b[(c % 3) * H_ + c / 3];
}
__global__ void zero_kernel(float* __restrict__ p, int n)
{
    int i = blockIdx.x * blockDim.x + threadIdx.x;
    if (i < n) p[i] = 0.f;
}

__global__ __launch_bounds__(256)
void ln_silu(const float* __restrict__ z,
             const float* __restrict__ lng,
             const float* __restrict__ lnb,
             float* __restrict__ out)
{
    __shared__ float red[256];
    int b = blockIdx.x, tid = threadIdx.x;
    const float* row = z + (size_t)b * H_;
    float s = 0.f, s2 = 0.f;
    for (int i = tid; i < H_; i += 256) { float v = row[i]; s += v; s2 += v * v; }
    red[tid] = s; __syncthreads();
    for (int o = 128; o > 0; o >>= 1) { if (tid < o) red[tid] += red[tid + o]; __syncthreads(); }
    float mu = red[0] / H_;
    __syncthreads();
    red[tid] = s2; __syncthreads();
    for (int o = 128; o > 0; o >>= 1) { if (tid < o) red[tid] += red[tid + o]; __syncthreads(); }
    float var = red[0] / H_ - mu * mu;
    float inv = rsqrtf(var + 1e-5f);
    for (int i = tid; i < H_; i += 256) {
        float y = (row[i] - mu) * inv * lng[i] + lnb[i];
        out[(size_t)b * H_ + i] = y / (1.f + expf(-y));
    }
}

__global__ __launch_bounds__(512)
void softmax_rebalance(const float* __restrict__ scores,
                       float* __restrict__ out)
{
    __shared__ float red[512];
    int b = blockIdx.x, tid = threadIdx.x;
    float s = (tid < N_) ? scores[(size_t)b * N_ + tid] : -INFINITY;
    if (s < 0.f) s = -INFINITY;
    red[tid] = s; __syncthreads();
    for (int o = 256; o > 0; o >>= 1) { if (tid < o) red[tid] = fmaxf(red[tid], red[tid + o]); __syncthreads(); }
    float m = red[0]; __syncthreads();
    float e = (tid < N_) ? expf(s - m) : 0.f;
    red[tid] = e; __syncthreads();
    for (int o = 256; o > 0; o >>= 1) { if (tid < o) red[tid] += red[tid + o]; __syncthreads(); }
    float S = red[0]; __syncthreads();
    float w = e / S;
    w = fminf(fmaxf(w, 0.0f), 0.1f);
    for (int it = 0; it < 20; it++) {
        red[tid] = (tid < N_) ? w : 0.f; __syncthreads();
        for (int o = 256; o > 0; o >>= 1) { if (tid < o) red[tid] += red[tid + o]; __syncthreads(); }
        float tot = red[0]; __syncthreads();
        float excess = tot - 1.0f;
        bool  active = excess > 1e-6f;
        float sur = fmaxf(w - 0.1f, 0.f);
        red[tid] = (tid < N_) ? sur : 0.f; __syncthreads();
        for (int o = 256; o > 0; o >>= 1) { if (tid < o) red[tid] += red[tid + o]; __syncthreads(); }
        float totsur = red[0]; __syncthreads();
        float upd = (totsur > 0.f)
                  ? w - sur / fmaxf(totsur, 1e-12f) * excess
                  : w - excess / (float)N_;
        upd = fminf(fmaxf(upd, 0.0f), 0.1f);
        if (active) w = upd;
    }
    if (tid < N_) out[(size_t)b * N_ + tid] = w;
}

// ===================== orchestration =====================
extern "C" void kernel_launch(void* const* d_in, const int* in_sizes, int n_in,
                              void* d_out, int out_size)
{
    const float* x     = (const float*)d_in[0];
    const float* w_ih0 = (const float*)d_in[1];
    const float* w_hh0 = (const float*)d_in[2];
    const float* b_ih0 = (const float*)d_in[3];
    const float* b_hh0 = (const float*)d_in[4];
    const float* w_ih1 = (const float*)d_in[5];
    const float* w_hh1 = (const float*)d_in[6];
    const float* b_ih1 = (const float*)d_in[7];
    const float* b_hh1 = (const float*)d_in[8];
    const float* w1    = (const float*)d_in[9];
    const float* b1    = (const float*)d_in[10];
    const float* ln_g  = (const float*)d_in[11];
    const float* ln_b  = (const float*)d_in[12];
    const float* w2    = (const float*)d_in[13];
    const float* b2    = (const float*)d_in[14];
    float* out = (float*)d_out;

    void* p;
    float *xproj, *seq, *h0, *h1, *z, *za, *scores;
    float *wih0p, *whh0p, *wih1p, *whh1p, *bih0p, *bhh0p, *bih1p, *bhh1p;
    cudaGetSymbolAddress(&p, g_xproj);  xproj  = (float*)p;
    cudaGetSymbolAddress(&p, g_seq);    seq    = (float*)p;
    cudaGetSymbolAddress(&p, g_h0);     h0     = (float*)p;
    cudaGetSymbolAddress(&p, g_h1);     h1     = (float*)p;
    cudaGetSymbolAddress(&p, g_z);      z      = (float*)p;
    cudaGetSymbolAddress(&p, g_za);     za     = (float*)p;
    cudaGetSymbolAddress(&p, g_scores); scores = (float*)p;
    cudaGetSymbolAddress(&p, g_wih0p);  wih0p  = (float*)p;
    cudaGetSymbolAddress(&p, g_whh0p);  whh0p  = (float*)p;
    cudaGetSymbolAddress(&p, g_wih1p);  wih1p  = (float*)p;
    cudaGetSymbolAddress(&p, g_whh1p);  whh1p  = (float*)p;
    cudaGetSymbolAddress(&p, g_bih0p);  bih0p  = (float*)p;
    cudaGetSymbolAddress(&p, g_bhh0p);  bhh0p  = (float*)p;
    cudaGetSymbolAddress(&p, g_bih1p);  bih1p  = (float*)p;
    cudaGetSymbolAddress(&p, g_bhh1p);  bhh1p  = (float*)p;

    // permute weights/biases into gate-interleaved layout (h*3+g)
    permute_w<<<dim3((N_ + 255) / 256, G3_), 256>>>(w_ih0, wih0p, N_);
    permute_w<<<dim3((H_ + 255) / 256, G3_), 256>>>(w_hh0, whh0p, H_);
    permute_w<<<dim3((H_ + 255) / 256, G3_), 256>>>(w_ih1, wih1p, H_);
    permute_w<<<dim3((H_ + 255) / 256, G3_), 256>>>(w_hh1, whh1p, H_);
    permute_b<<<(G3_ + 255) / 256, 256>>>(b_ih0, bih0p);
    permute_b<<<(G3_ + 255) / 256, 256>>>(b_hh0, bhh0p);
    permute_b<<<(G3_ + 255) / 256, 256>>>(b_ih1, bih1p);
    permute_b<<<(G3_ + 255) / 256, 256>>>(b_hh1, bhh1p);

    // layer 0 input projection: xproj = x @ wih0p^T + bih0p
    gemm_db<<<dim3(G3_ / BN, BT_ / BM), NT>>>(
        x, wih0p, bih0p, xproj, nullptr, nullptr, nullptr, nullptr, BT_, G3_, N_, 0, 0);
    zero_kernel<<<(B_ * H_ + 255) / 256, 256>>>(h0, B_ * H_);

    // layer 0 recurrence (fused GEMM + gates)
    for (int t = 0; t < T_; t++) {
        float* hin  = (t & 1) ? h1 : h0;
        float* hout = (t & 1) ? h0 : h1;
        gemm_db<<<dim3(G3_ / BN, B_ / BM), NT>>>(
            hin, whh0p, bhh0p, nullptr, xproj, hin, hout, seq, B_, G3_, H_, t, 1);
    }

    // layer 1 input projection
    gemm_db<<<dim3(G3_ / BN, BT_ / BM), NT>>>(
        seq, wih1p, bih1p, xproj, nullptr, nullptr, nullptr, nullptr, BT_, G3_, H_, 0, 0);
    zero_kernel<<<(B_ * H_ + 255) / 256, 256>>>(h0, B_ * H_);

    // layer 1 recurrence
    for (int t = 0; t < T_; t++) {
        float* hin  = (t & 1) ? h1 : h0;
        float* hout = (t & 1) ? h0 : h1;
        gemm_db<<<dim3(G3_ / BN, B_ / BM), NT>>>(
            hin, whh1p, bhh1p, nullptr, xproj, hin, hout, nullptr, B_, G3_, H_, t, 1);
    }

    // head
    gemm_db<<<dim3((H_ + BN - 1) / BN, B_ / BM), NT>>>(
        h0, w1, b1, z, nullptr, nullptr, nullptr, nullptr, B_, H_, H_, 0, 0);
    ln_silu<<<B_, 256>>>(z, ln_g, ln_b, za);
    gemm_db<<<dim3((N_ + BN - 1) / BN, B_ / BM), NT>>>(
        za, w2, b2, scores, nullptr, nullptr, nullptr, nullptr, B_, N_, H_, 0, 0);
    softmax_rebalance<<<B_, 512>>>(scores, out);
}